// round 7
// baseline (speedup 1.0000x reference)
#include <cuda_runtime.h>
#include <math.h>
#include <stdint.h>

#define Bn   256
#define Ln   512
#define EMB  100
#define HID  128
#define G4   512          // 4*HID
#define TAGS 17
#define BL   (Bn*Ln)      // 131072
#define KSM  64           // W_hh k-rows in smem
#define KRG  64           // W_hh k-rows in registers

// ---------------- scratch (device globals: allocation-free, per rules) ----------------
__device__ float g_xg[2 * BL * G4];     // input-gate preactivations, both dirs
__device__ float g_hf[BL * HID];        // forward hidden states
__device__ float g_hb[BL * HID];        // backward hidden states
__device__ float g_em[BL * TAGS];       // emissions
__device__ float g_WihT[EMB * 1024];    // W_ih transposed, dirs concatenated on cols
__device__ float g_WhhP[2 * HID * G4];  // W_hh k-major, columns PERMUTED: col t <- q*128+k
__device__ float g_bias[1024];          // b_f ++ b_b
__device__ int   g_dummy;

// ---------------- packed f32x2 helpers (xg kernel) ----------------
__device__ __forceinline__ uint64_t pack2(float lo, float hi) {
    uint64_t r;
    asm("mov.b64 %0, {%1, %2};" : "=l"(r) : "f"(lo), "f"(hi));
    return r;
}
__device__ __forceinline__ float2 unpack2(uint64_t v) {
    float lo, hi;
    asm("mov.b64 {%0, %1}, %2;" : "=f"(lo), "=f"(hi) : "l"(v));
    return make_float2(lo, hi);
}
__device__ __forceinline__ void ffma2(uint64_t& acc, uint64_t a, uint64_t b) {
    asm("fma.rn.f32x2 %0, %1, %2, %0;" : "+l"(acc) : "l"(a), "l"(b));
}

__device__ __forceinline__ float sel4(float v0, float v1, float v2, float v3, int i) {
    float r = v0;
    r = (i == 1) ? v1 : r;
    r = (i == 2) ? v2 : r;
    r = (i == 3) ? v3 : r;
    return r;
}

// ---------------- dummy (shifts ncu capture slot onto lstm_kernel) ----------------
__global__ void dummy_kernel() { if (threadIdx.x == 1024) g_dummy = 1; }

// ---------------- prep: transpose/permute weights ----------------
__global__ void prep_kernel(const float* __restrict__ Wihf, const float* __restrict__ Whhf,
                            const float* __restrict__ bf,   const float* __restrict__ Wihb,
                            const float* __restrict__ Whhb, const float* __restrict__ bb) {
    int i = blockIdx.x * blockDim.x + threadIdx.x;
    int stride = gridDim.x * blockDim.x;
    for (int idx = i; idx < EMB * 1024; idx += stride) {
        int e = idx >> 10, c = idx & 1023, d = c >> 9, j = c & 511;
        g_WihT[idx] = (d ? Wihb : Wihf)[j * EMB + e];
    }
    // permuted: g_WhhP[d][kk][t] = Whh_d[(t&3)*128 + (t>>2)][kk]
    for (int idx = i; idx < 2 * HID * G4; idx += stride) {
        int d = idx >> 16, r = idx & 65535, kk = r >> 9, t = r & 511;
        int j = (t & 3) * 128 + (t >> 2);
        g_WhhP[idx] = (d ? Whhb : Whhf)[j * HID + kk];
    }
    for (int idx = i; idx < 1024; idx += stride) {
        int d = idx >> 9, j = idx & 511;
        g_bias[idx] = (d ? bb : bf)[j];
    }
}

// ---------------- embed + input projection: xg = emb[ids] @ W_ih^T + b ----------------
__global__ void __launch_bounds__(256) xg_kernel(const int* __restrict__ ids,
                                                 const float* __restrict__ emb) {
    __shared__ int   ids_s[64];
    __shared__ float xs[64 * EMB];
    int tid = threadIdx.x;
    int rbase = blockIdx.y * 64;
    int cbase = blockIdx.x * 128;

    if (tid < 64) ids_s[tid] = ids[rbase + tid];
    __syncthreads();
    for (int i = tid; i < 64 * EMB; i += 256) {
        int r = i / EMB, e = i - r * EMB;
        xs[i] = emb[ids_s[r] * EMB + e];
    }
    __syncthreads();

    int tx = tid & 31, ty = tid >> 5;
    int c0 = cbase + tx * 4;

    uint64_t accA[8], accB[8];
    uint64_t z = pack2(0.f, 0.f);
#pragma unroll
    for (int i = 0; i < 8; i++) { accA[i] = z; accB[i] = z; }

    const float* xrow = xs + (ty * 8) * EMB;
    for (int e = 0; e < EMB; e++) {
        ulonglong2 w2 = *(const ulonglong2*)&g_WihT[e * 1024 + c0];
#pragma unroll
        for (int i = 0; i < 8; i++) {
            float xv = xrow[i * EMB + e];
            uint64_t xx = pack2(xv, xv);
            ffma2(accA[i], xx, w2.x);
            ffma2(accB[i], xx, w2.y);
        }
    }

    int d  = c0 >> 9;
    int jj = c0 & 511;
    float4 bias = *(const float4*)&g_bias[c0];
#pragma unroll
    for (int i = 0; i < 8; i++) {
        int row = rbase + ty * 8 + i;
        float2 vA = unpack2(accA[i]);
        float2 vB = unpack2(accB[i]);
        float4 o;
        o.x = vA.x + bias.x; o.y = vA.y + bias.y;
        o.z = vB.x + bias.z; o.w = vB.y + bias.w;
        *(float4*)&g_xg[(d * BL + row) * 512 + jj] = o;
    }
}

// ---------------- persistent bidirectional LSTM: single barrier + double-buffered h ----
// Grid 128: dir = bid&1, 4 batch elements per CTA, 512 threads.
// Thread t: gate-type q=t&3 of unit k=t>>2 in the matvec; 4x4 in-quad shfl transpose
// hands it the 4 gates of (b=q, k) for the cell update. h double-buffered so the
// step's hbuf reads and writes never share a buffer -> one __syncthreads per step.
extern __shared__ float lsmem[];
__device__ __forceinline__ float sigf(float x) { return 1.f / (1.f + expf(-x)); }

__global__ void __launch_bounds__(512, 1) lstm_kernel() {
    float* Wc    = lsmem;               // KSM*512
    float* hbuf0 = lsmem + KSM * 512;   // 512 (16B aligned)
    float* hbuf1 = hbuf0 + 512;         // 512

    int tid   = threadIdx.x;
    int lane  = tid & 31;
    int q     = tid & 3;       // gate type (i,f,g,o); post-transpose, batch idx
    int k     = tid >> 2;      // hidden unit
    int dir   = blockIdx.x & 1;
    int bbase = (blockIdx.x >> 1) * 4;

    const float* Wt = g_WhhP + dir * (HID * G4);
    for (int i = tid; i < KSM * 512; i += 512) Wc[i] = Wt[i];
    hbuf0[tid] = 0.f;

    float wreg[KRG];
#pragma unroll
    for (int kk = 0; kk < KRG; kk++)
        wreg[kk] = Wt[(KSM + kk) * 512 + tid];

    float creg = 0.f;
    const float* xgbase = g_xg + dir * (BL * G4);
    float* hout = dir ? g_hb : g_hf;

    int gcol = q * 128 + k;    // logical gate column this thread accumulates
    int tt0 = dir ? (Ln - 1) : 0;
    int step_dt = dir ? -512 : 512;
    int off0 = ((bbase + 0) * Ln + tt0) * 512 + gcol;
    int off1 = ((bbase + 1) * Ln + tt0) * 512 + gcol;
    int off2 = ((bbase + 2) * Ln + tt0) * 512 + gcol;
    int off3 = ((bbase + 3) * Ln + tt0) * 512 + gcol;

    float cxg0 = xgbase[off0], cxg1 = xgbase[off1];
    float cxg2 = xgbase[off2], cxg3 = xgbase[off3];
    __syncthreads();

    const float* wp = Wc + tid;
    float* hr = hbuf0;   // read buffer (h from step s-1)
    float* hw = hbuf1;   // write buffer (h for step s)
    for (int s = 0; s < Ln; s++) {
        // prefetch next step's xg
        float nxg0 = 0.f, nxg1 = 0.f, nxg2 = 0.f, nxg3 = 0.f;
        if (s + 1 < Ln) {
            nxg0 = xgbase[off0 + step_dt];
            nxg1 = xgbase[off1 + step_dt];
            nxg2 = xgbase[off2 + step_dt];
            nxg3 = xgbase[off3 + step_dt];
        }

        // ---- gate dot products: a_b = xg_b + sum_kk h[b][kk] * W[gcol][kk] ----
        float a0 = cxg0, a1 = cxg1, a2 = cxg2, a3 = cxg3;
#pragma unroll 8
        for (int kk = 0; kk < KSM; kk++) {
            float4 h4 = *(const float4*)(hr + kk * 4);
            float  w  = wp[kk * 512];
            a0 += h4.x * w; a1 += h4.y * w; a2 += h4.z * w; a3 += h4.w * w;
        }
#pragma unroll 16
        for (int kk = 0; kk < KRG; kk++) {
            float4 h4 = *(const float4*)(hr + (KSM + kk) * 4);
            float  w  = wreg[kk];
            a0 += h4.x * w; a1 += h4.y * w; a2 += h4.z * w; a3 += h4.w * w;
        }

        // ---- 4x4 transpose within the lane quad ----
        float gt0 = 0.f, gt1 = 0.f, gt2 = 0.f, gt3 = 0.f;
#pragma unroll
        for (int r = 0; r < 4; r++) {
            int is  = (q - r) & 3;
            float y = sel4(a0, a1, a2, a3, is);
            int src = (lane & ~3) | ((q + r) & 3);
            float rec = __shfl_sync(0xffffffffu, y, src);
            int jj  = (q + r) & 3;
            gt0 = (jj == 0) ? rec : gt0;
            gt1 = (jj == 1) ? rec : gt1;
            gt2 = (jj == 2) ? rec : gt2;
            gt3 = (jj == 3) ? rec : gt3;
        }

        // ---- cell update for (b=q, k) ----
        creg = sigf(gt1) * creg + sigf(gt0) * tanhf(gt2);
        float h = sigf(gt3) * tanhf(creg);
        hw[tid] = h;                                  // hw[k*4 + b] == hw[tid]
        int tt = dir ? (Ln - 1 - s) : s;
        hout[((bbase + q) * Ln + tt) * HID + k] = h;
        __syncthreads();                               // publishes hw for next step

        float* tmp = hr; hr = hw; hw = tmp;            // swap buffers
        cxg0 = nxg0; cxg1 = nxg1; cxg2 = nxg2; cxg3 = nxg3;
        off0 += step_dt; off1 += step_dt; off2 += step_dt; off3 += step_dt;
    }
}

// ---------------- FC: emissions = [h_f, h_b] @ fc_W^T + fc_b ----------------
__global__ void __launch_bounds__(256) fc_kernel(const float* __restrict__ fcW,
                                                 const float* __restrict__ fcb) {
    int warp = (blockIdx.x * blockDim.x + threadIdx.x) >> 5;
    int lane = threadIdx.x & 31;
    if (warp >= BL) return;
    float4 hf = *(const float4*)&g_hf[warp * HID + lane * 4];
    float4 hb = *(const float4*)&g_hb[warp * HID + lane * 4];
#pragma unroll
    for (int t = 0; t < TAGS; t++) {
        float4 wf = *(const float4*)&fcW[t * 256 + lane * 4];
        float4 wb = *(const float4*)&fcW[t * 256 + 128 + lane * 4];
        float s = hf.x * wf.x + hf.y * wf.y + hf.z * wf.z + hf.w * wf.w
                + hb.x * wb.x + hb.y * wb.y + hb.z * wb.z + hb.w * wb.w;
#pragma unroll
        for (int off = 16; off; off >>= 1) s += __shfl_xor_sync(0xffffffffu, s, off);
        if (lane == 0) g_em[warp * TAGS + t] = s + fcb[t];
    }
}

// ---------------- Viterbi: one warp per batch element; float32 output ----------------
__global__ void __launch_bounds__(128) viterbi_kernel(const int* __restrict__ ids,
                                                      const float* __restrict__ trans,
                                                      const float* __restrict__ start_t,
                                                      const float* __restrict__ end_t,
                                                      float* __restrict__ out) {
    __shared__ unsigned char hist[4][Ln * 20];
    int w = threadIdx.x >> 5, lane = threadIdx.x & 31;
    int b = blockIdx.x * 4 + w;
    const float NEG = -3e38f;

    float tcol[TAGS];
#pragma unroll
    for (int i = 0; i < TAGS; i++)
        tcol[i] = (lane < TAGS) ? trans[i * TAGS + lane] : 0.f;

    const float* emrow = g_em + b * Ln * TAGS;
    const int*   idrow = ids + b * Ln;

    float score = (lane < TAGS) ? start_t[lane] + emrow[lane] : NEG;

    for (int t = 1; t < Ln; t++) {
        float em = (lane < TAGS) ? emrow[t * TAGS + lane] : 0.f;
        int mask = (idrow[t] != 0);
        float best = NEG; int bi = 0;
#pragma unroll
        for (int i = 0; i < TAGS; i++) {
            float si = __shfl_sync(0xffffffffu, score, i);
            float v = si + tcol[i];
            if (v > best) { best = v; bi = i; }   // first max wins (matches jnp.argmax)
        }
        int idx;
        if (mask) { if (lane < TAGS) score = best + em; idx = bi; }
        else      { idx = lane; }                  // identity backpointer on pads
        if (lane < TAGS) hist[w][t * 20 + lane] = (unsigned char)idx;
    }

    float fin = (lane < TAGS) ? score + end_t[lane] : NEG;
    int fid = lane;
#pragma unroll
    for (int off = 16; off; off >>= 1) {
        float ov = __shfl_xor_sync(0xffffffffu, fin, off);
        int   oi = __shfl_xor_sync(0xffffffffu, fid, off);
        if (ov > fin || (ov == fin && oi < fid)) { fin = ov; fid = oi; }
    }
    __syncwarp();

    if (lane == 0) {
        int tag = fid;
        float* orow = out + b * Ln;
        orow[Ln - 1] = (idrow[Ln - 1] != 0) ? (float)tag : 0.f;
        for (int t = Ln - 2; t >= 0; t--) {
            tag = hist[w][(t + 1) * 20 + tag];
            orow[t] = (idrow[t] != 0) ? (float)tag : 0.f;
        }
    }
}

// ---------------- launch ----------------
extern "C" void kernel_launch(void* const* d_in, const int* in_sizes, int n_in,
                              void* d_out, int out_size) {
    const void* p[13];
    for (int i = 0; i < 13; i++) p[i] = 0;
    int c51200 = 0, c65536 = 0, c512 = 0, c17 = 0;
    for (int i = 0; i < n_in; i++) {
        switch (in_sizes[i]) {
            case 131072:  p[0] = d_in[i]; break;
            case 3000000: p[1] = d_in[i]; break;
            case 51200:   p[(c51200++ == 0) ? 2 : 5] = d_in[i]; break;
            case 65536:   p[(c65536++ == 0) ? 3 : 6] = d_in[i]; break;
            case 512:     p[(c512++   == 0) ? 4 : 7] = d_in[i]; break;
            case 4352:    p[8]  = d_in[i]; break;
            case 289:     p[10] = d_in[i]; break;
            case 17: {
                int k = c17++;
                p[(k == 0) ? 9 : ((k == 1) ? 11 : 12)] = d_in[i];
                break;
            }
            default: break;
        }
    }
    const int*   input_ids = (const int*)  p[0];
    const float* emb       = (const float*)p[1];
    const float* Wihf      = (const float*)p[2];
    const float* Whhf      = (const float*)p[3];
    const float* bf        = (const float*)p[4];
    const float* Wihb      = (const float*)p[5];
    const float* Whhb      = (const float*)p[6];
    const float* bb        = (const float*)p[7];
    const float* fcW       = (const float*)p[8];
    const float* fcb       = (const float*)p[9];
    const float* trans     = (const float*)p[10];
    const float* startt    = (const float*)p[11];
    const float* endt      = (const float*)p[12];
    float* out = (float*)d_out;

    prep_kernel<<<64, 256>>>(Wihf, Whhf, bf, Wihb, Whhb, bb);
    xg_kernel<<<dim3(8, 2048), 256>>>(input_ids, emb);
    dummy_kernel<<<1, 32>>>();   // shifts ncu capture slot onto lstm_kernel

    const int lsmem_bytes = (KSM * 512 + 1024) * (int)sizeof(float); // 135168
    cudaFuncSetAttribute(lstm_kernel, cudaFuncAttributeMaxDynamicSharedMemorySize,
                         lsmem_bytes);
    lstm_kernel<<<128, 512, lsmem_bytes>>>();

    fc_kernel<<<16384, 256>>>(fcW, fcb);
    viterbi_kernel<<<64, 128>>>(input_ids, trans, startt, endt, out);
}

// round 8
// speedup vs baseline: 1.1479x; 1.1479x over previous
#include <cuda_runtime.h>
#include <math.h>
#include <stdint.h>

#define Bn   256
#define Ln   512
#define EMB  100
#define HID  128
#define G4   512          // 4*HID
#define TAGS 17
#define BL   (Bn*Ln)      // 131072
#define KSM  48           // smem W rows per k-half
#define KRG  16           // register W rows per k-half

// ---------------- scratch (device globals: allocation-free, per rules) ----------------
__device__ float g_xg[2 * BL * G4];     // input-gate preactivations, both dirs
__device__ float g_hf[BL * HID];        // forward hidden states
__device__ float g_hb[BL * HID];        // backward hidden states
__device__ float g_em[BL * TAGS];       // emissions
__device__ float g_WihT[EMB * 1024];    // W_ih transposed, dirs concatenated on cols
__device__ float g_WhhT[2 * HID * G4];  // W_hh transposed (k-major), per dir
__device__ float g_bias[1024];          // b_f ++ b_b

// ---------------- packed f32x2 helpers (xg kernel) ----------------
__device__ __forceinline__ uint64_t pack2(float lo, float hi) {
    uint64_t r;
    asm("mov.b64 %0, {%1, %2};" : "=l"(r) : "f"(lo), "f"(hi));
    return r;
}
__device__ __forceinline__ float2 unpack2(uint64_t v) {
    float lo, hi;
    asm("mov.b64 {%0, %1}, %2;" : "=f"(lo), "=f"(hi) : "l"(v));
    return make_float2(lo, hi);
}
__device__ __forceinline__ void ffma2(uint64_t& acc, uint64_t a, uint64_t b) {
    asm("fma.rn.f32x2 %0, %1, %2, %0;" : "+l"(acc) : "l"(a), "l"(b));
}

// ---------------- prep: transpose weights ----------------
__global__ void prep_kernel(const float* __restrict__ Wihf, const float* __restrict__ Whhf,
                            const float* __restrict__ bf,   const float* __restrict__ Wihb,
                            const float* __restrict__ Whhb, const float* __restrict__ bb) {
    int i = blockIdx.x * blockDim.x + threadIdx.x;
    int stride = gridDim.x * blockDim.x;
    for (int idx = i; idx < EMB * 1024; idx += stride) {
        int e = idx >> 10, c = idx & 1023, d = c >> 9, j = c & 511;
        g_WihT[idx] = (d ? Wihb : Wihf)[j * EMB + e];
    }
    for (int idx = i; idx < 2 * HID * G4; idx += stride) {
        int d = idx >> 16, r = idx & 65535, k = r >> 9, j = r & 511;
        g_WhhT[idx] = (d ? Whhb : Whhf)[j * HID + k];
    }
    for (int idx = i; idx < 1024; idx += stride) {
        int d = idx >> 9, j = idx & 511;
        g_bias[idx] = (d ? bb : bf)[j];
    }
}

// ---------------- embed + input projection: xg = emb[ids] @ W_ih^T + b ----------------
__global__ void __launch_bounds__(256) xg_kernel(const int* __restrict__ ids,
                                                 const float* __restrict__ emb) {
    __shared__ int   ids_s[64];
    __shared__ float xs[64 * EMB];
    int tid = threadIdx.x;
    int rbase = blockIdx.y * 64;
    int cbase = blockIdx.x * 128;

    if (tid < 64) ids_s[tid] = ids[rbase + tid];
    __syncthreads();
    for (int i = tid; i < 64 * EMB; i += 256) {
        int r = i / EMB, e = i - r * EMB;
        xs[i] = emb[ids_s[r] * EMB + e];
    }
    __syncthreads();

    int tx = tid & 31, ty = tid >> 5;
    int c0 = cbase + tx * 4;

    uint64_t accA[8], accB[8];
    uint64_t z = pack2(0.f, 0.f);
#pragma unroll
    for (int i = 0; i < 8; i++) { accA[i] = z; accB[i] = z; }

    const float* xrow = xs + (ty * 8) * EMB;
    for (int e = 0; e < EMB; e++) {
        ulonglong2 w2 = *(const ulonglong2*)&g_WihT[e * 1024 + c0];
#pragma unroll
        for (int i = 0; i < 8; i++) {
            float xv = xrow[i * EMB + e];
            uint64_t xx = pack2(xv, xv);
            ffma2(accA[i], xx, w2.x);
            ffma2(accB[i], xx, w2.y);
        }
    }

    int d  = c0 >> 9;
    int jj = c0 & 511;
    float4 bias = *(const float4*)&g_bias[c0];
#pragma unroll
    for (int i = 0; i < 8; i++) {
        int row = rbase + ty * 8 + i;
        float2 vA = unpack2(accA[i]);
        float2 vB = unpack2(accB[i]);
        float4 o;
        o.x = vA.x + bias.x; o.y = vA.y + bias.y;
        o.z = vB.x + bias.z; o.w = vB.y + bias.w;
        *(float4*)&g_xg[(d * BL + row) * 512 + jj] = o;
    }
}

// ---------------- persistent bidirectional LSTM: 1024 threads, split-k ----------------
// Grid 128: dir = bid&1, 4 batch elements per CTA.
// Thread t: gcol = t&511, half = t>>9 (k-range [half*64, half*64+64)).
// Phase 1: each half computes its partial gate dot products -> part[half][gcol*4+b].
// Phase 2: threads t<512 (b=t&3, k=t>>2) combine halves and do the cell update.
// smem: Wc[2*KSM][512] (196KB) + part[2][2048] (16KB) + hbuf[512] (2KB) = 210KB
extern __shared__ float lsmem[];
__device__ __forceinline__ float sigf(float x) { return 1.f / (1.f + expf(-x)); }

__global__ void __launch_bounds__(1024, 1) lstm_kernel() {
    float* Wc   = lsmem;                       // 2*KSM*512
    float* part = lsmem + 2 * KSM * 512;       // 2*2048
    float* hbuf = part + 4096;                 // 512 (16B aligned)

    int tid   = threadIdx.x;
    int gcol  = tid & 511;
    int half  = tid >> 9;
    int dir   = blockIdx.x & 1;
    int bbase = (blockIdx.x >> 1) * 4;

    const float* Wt = g_WhhT + dir * (HID * G4);

    // cooperative smem load: Wc row r <- global row (r<KSM ? r : r-KSM+64)
    for (int i = tid; i < 2 * KSM * 512; i += 1024) {
        int r = i >> 9, c = i & 511;
        int gr = (r < KSM) ? r : (r - KSM + 64);
        Wc[i] = Wt[gr * 512 + c];
    }
    if (tid < 512) hbuf[tid] = 0.f;

    // register W rows: global rows half*64 + KSM + kk
    float wreg[KRG];
#pragma unroll
    for (int kk = 0; kk < KRG; kk++)
        wreg[kk] = Wt[(half * 64 + KSM + kk) * 512 + gcol];

    float creg = 0.f;
    const float* xgbase = g_xg + dir * (BL * G4);
    float* hout = dir ? g_hb : g_hf;

    int tt0 = dir ? (Ln - 1) : 0;
    int step_dt = dir ? -512 : 512;
    int off0 = ((bbase + 0) * Ln + tt0) * 512 + gcol;
    int off1 = ((bbase + 1) * Ln + tt0) * 512 + gcol;
    int off2 = ((bbase + 2) * Ln + tt0) * 512 + gcol;
    int off3 = ((bbase + 3) * Ln + tt0) * 512 + gcol;

    float cxg0 = 0.f, cxg1 = 0.f, cxg2 = 0.f, cxg3 = 0.f;
    if (half == 0) {                 // only half 0 folds xg into its partial
        cxg0 = xgbase[off0]; cxg1 = xgbase[off1];
        cxg2 = xgbase[off2]; cxg3 = xgbase[off3];
    }
    __syncthreads();

    const float*  wp  = Wc + half * (KSM * 512) + gcol;
    const float4* hb4 = (const float4*)hbuf + half * 64;   // this half's k-range
    int b2 = tid & 3, k2 = tid >> 2;                       // phase-2 mapping (tid<512)
    float* partw = part + half * 2048 + gcol * 4;

    for (int s = 0; s < Ln; s++) {
        // prefetch next step's xg (half 0 only; hidden under the dot-product loop)
        float nxg0 = 0.f, nxg1 = 0.f, nxg2 = 0.f, nxg3 = 0.f;
        if (half == 0 && s + 1 < Ln) {
            nxg0 = xgbase[off0 + step_dt];
            nxg1 = xgbase[off1 + step_dt];
            nxg2 = xgbase[off2 + step_dt];
            nxg3 = xgbase[off3 + step_dt];
        }

        // ---- phase 1: partial gate dot products over this half's 64 k ----
        float a0 = cxg0, a1 = cxg1, a2 = cxg2, a3 = cxg3;
#pragma unroll 8
        for (int kk = 0; kk < KSM; kk++) {
            float4 h4 = hb4[kk];                 // broadcast within warp
            float  w  = wp[kk * 512];
            a0 += h4.x * w; a1 += h4.y * w; a2 += h4.z * w; a3 += h4.w * w;
        }
#pragma unroll
        for (int kk = 0; kk < KRG; kk++) {
            float4 h4 = hb4[KSM + kk];
            float  w  = wreg[kk];
            a0 += h4.x * w; a1 += h4.y * w; a2 += h4.z * w; a3 += h4.w * w;
        }
        float4 pv; pv.x = a0; pv.y = a1; pv.z = a2; pv.w = a3;
        *(float4*)partw = pv;                     // conflict-free STS.128
        __syncthreads();

        // ---- phase 2: combine halves + cell update for (b2, k2) ----
        if (tid < 512) {
            float gi = part[k2 * 4 + b2]           + part[2048 + k2 * 4 + b2];
            float gf = part[512  + k2 * 4 + b2]    + part[2560 + k2 * 4 + b2];
            float gg = part[1024 + k2 * 4 + b2]    + part[3072 + k2 * 4 + b2];
            float go = part[1536 + k2 * 4 + b2]    + part[3584 + k2 * 4 + b2];
            creg = sigf(gf) * creg + sigf(gi) * tanhf(gg);
            float h = sigf(go) * tanhf(creg);
            hbuf[tid] = h;                         // hbuf[k2*4 + b2] == hbuf[tid]
            int tt = dir ? (Ln - 1 - s) : s;
            hout[((bbase + b2) * Ln + tt) * HID + k2] = h;
        }
        __syncthreads();

        cxg0 = nxg0; cxg1 = nxg1; cxg2 = nxg2; cxg3 = nxg3;
        off0 += step_dt; off1 += step_dt; off2 += step_dt; off3 += step_dt;
    }
}

// ---------------- FC: emissions = [h_f, h_b] @ fc_W^T + fc_b ----------------
__global__ void __launch_bounds__(256) fc_kernel(const float* __restrict__ fcW,
                                                 const float* __restrict__ fcb) {
    int warp = (blockIdx.x * blockDim.x + threadIdx.x) >> 5;
    int lane = threadIdx.x & 31;
    if (warp >= BL) return;
    float4 hf = *(const float4*)&g_hf[warp * HID + lane * 4];
    float4 hb = *(const float4*)&g_hb[warp * HID + lane * 4];
#pragma unroll
    for (int t = 0; t < TAGS; t++) {
        float4 wf = *(const float4*)&fcW[t * 256 + lane * 4];
        float4 wb = *(const float4*)&fcW[t * 256 + 128 + lane * 4];
        float s = hf.x * wf.x + hf.y * wf.y + hf.z * wf.z + hf.w * wf.w
                + hb.x * wb.x + hb.y * wb.y + hb.z * wb.z + hb.w * wb.w;
#pragma unroll
        for (int off = 16; off; off >>= 1) s += __shfl_xor_sync(0xffffffffu, s, off);
        if (lane == 0) g_em[warp * TAGS + t] = s + fcb[t];
    }
}

// ---------------- Viterbi: one warp per batch element; float32 output ----------------
__global__ void __launch_bounds__(128) viterbi_kernel(const int* __restrict__ ids,
                                                      const float* __restrict__ trans,
                                                      const float* __restrict__ start_t,
                                                      const float* __restrict__ end_t,
                                                      float* __restrict__ out) {
    __shared__ unsigned char hist[4][Ln * 20];
    int w = threadIdx.x >> 5, lane = threadIdx.x & 31;
    int b = blockIdx.x * 4 + w;
    const float NEG = -3e38f;

    float tcol[TAGS];
#pragma unroll
    for (int i = 0; i < TAGS; i++)
        tcol[i] = (lane < TAGS) ? trans[i * TAGS + lane] : 0.f;

    const float* emrow = g_em + b * Ln * TAGS;
    const int*   idrow = ids + b * Ln;

    float score = (lane < TAGS) ? start_t[lane] + emrow[lane] : NEG;

    for (int t = 1; t < Ln; t++) {
        float em = (lane < TAGS) ? emrow[t * TAGS + lane] : 0.f;
        int mask = (idrow[t] != 0);
        float best = NEG; int bi = 0;
#pragma unroll
        for (int i = 0; i < TAGS; i++) {
            float si = __shfl_sync(0xffffffffu, score, i);
            float v = si + tcol[i];
            if (v > best) { best = v; bi = i; }   // first max wins (matches jnp.argmax)
        }
        int idx;
        if (mask) { if (lane < TAGS) score = best + em; idx = bi; }
        else      { idx = lane; }                  // identity backpointer on pads
        if (lane < TAGS) hist[w][t * 20 + lane] = (unsigned char)idx;
    }

    float fin = (lane < TAGS) ? score + end_t[lane] : NEG;
    int fid = lane;
#pragma unroll
    for (int off = 16; off; off >>= 1) {
        float ov = __shfl_xor_sync(0xffffffffu, fin, off);
        int   oi = __shfl_xor_sync(0xffffffffu, fid, off);
        if (ov > fin || (ov == fin && oi < fid)) { fin = ov; fid = oi; }
    }
    __syncwarp();

    if (lane == 0) {
        int tag = fid;
        float* orow = out + b * Ln;
        orow[Ln - 1] = (idrow[Ln - 1] != 0) ? (float)tag : 0.f;
        for (int t = Ln - 2; t >= 0; t--) {
            tag = hist[w][(t + 1) * 20 + tag];
            orow[t] = (idrow[t] != 0) ? (float)tag : 0.f;
        }
    }
}

// ---------------- launch ----------------
extern "C" void kernel_launch(void* const* d_in, const int* in_sizes, int n_in,
                              void* d_out, int out_size) {
    const void* p[13];
    for (int i = 0; i < 13; i++) p[i] = 0;
    int c51200 = 0, c65536 = 0, c512 = 0, c17 = 0;
    for (int i = 0; i < n_in; i++) {
        switch (in_sizes[i]) {
            case 131072:  p[0] = d_in[i]; break;
            case 3000000: p[1] = d_in[i]; break;
            case 51200:   p[(c51200++ == 0) ? 2 : 5] = d_in[i]; break;
            case 65536:   p[(c65536++ == 0) ? 3 : 6] = d_in[i]; break;
            case 512:     p[(c512++   == 0) ? 4 : 7] = d_in[i]; break;
            case 4352:    p[8]  = d_in[i]; break;
            case 289:     p[10] = d_in[i]; break;
            case 17: {
                int k = c17++;
                p[(k == 0) ? 9 : ((k == 1) ? 11 : 12)] = d_in[i];
                break;
            }
            default: break;
        }
    }
    const int*   input_ids = (const int*)  p[0];
    const float* emb       = (const float*)p[1];
    const float* Wihf      = (const float*)p[2];
    const float* Whhf      = (const float*)p[3];
    const float* bf        = (const float*)p[4];
    const float* Wihb      = (const float*)p[5];
    const float* Whhb      = (const float*)p[6];
    const float* bb        = (const float*)p[7];
    const float* fcW       = (const float*)p[8];
    const float* fcb       = (const float*)p[9];
    const float* trans     = (const float*)p[10];
    const float* startt    = (const float*)p[11];
    const float* endt      = (const float*)p[12];
    float* out = (float*)d_out;

    prep_kernel<<<64, 256>>>(Wihf, Whhf, bf, Wihb, Whhb, bb);
    xg_kernel<<<dim3(8, 2048), 256>>>(input_ids, emb);

    const int lsmem_bytes = (2 * KSM * 512 + 4096 + 512) * (int)sizeof(float); // 215040
    cudaFuncSetAttribute(lstm_kernel, cudaFuncAttributeMaxDynamicSharedMemorySize,
                         lsmem_bytes);
    lstm_kernel<<<128, 1024, lsmem_bytes>>>();

    fc_kernel<<<16384, 256>>>(fcW, fcb);
    viterbi_kernel<<<64, 128>>>(input_ids, trans, startt, endt, out);
}

// round 9
// speedup vs baseline: 1.5140x; 1.3190x over previous
#include <cuda_runtime.h>
#include <math.h>
#include <stdint.h>

#define Bn   256
#define Ln   512
#define VOCAB 30000
#define EMB  100
#define HID  128
#define G4   512          // 4*HID
#define TAGS 17
#define BL   (Bn*Ln)      // 131072
#define KSM  48           // smem W rows per k-half
#define KRG  16           // register W rows per k-half

// ---------------- scratch (device globals: allocation-free, per rules) ----------------
__device__ float g_proj[VOCAB * 1024];  // 123MB: per-vocab gate preactivations, both dirs
__device__ float g_hf[BL * HID];        // forward hidden states
__device__ float g_hb[BL * HID];        // backward hidden states
__device__ float g_em[BL * TAGS];       // emissions
__device__ float g_WihT[EMB * 1024];    // W_ih transposed, dirs concatenated on cols
__device__ float g_WhhT[2 * HID * G4];  // W_hh transposed (k-major), per dir
__device__ float g_bias[1024];          // b_f ++ b_b

// ---------------- packed f32x2 helpers ----------------
__device__ __forceinline__ uint64_t pack2(float lo, float hi) {
    uint64_t r;
    asm("mov.b64 %0, {%1, %2};" : "=l"(r) : "f"(lo), "f"(hi));
    return r;
}
__device__ __forceinline__ float2 unpack2(uint64_t v) {
    float lo, hi;
    asm("mov.b64 {%0, %1}, %2;" : "=f"(lo), "=f"(hi) : "l"(v));
    return make_float2(lo, hi);
}
__device__ __forceinline__ void ffma2(uint64_t& acc, uint64_t a, uint64_t b) {
    asm("fma.rn.f32x2 %0, %1, %2, %0;" : "+l"(acc) : "l"(a), "l"(b));
}

// ---------------- prep: transpose weights ----------------
__global__ void prep_kernel(const float* __restrict__ Wihf, const float* __restrict__ Whhf,
                            const float* __restrict__ bf,   const float* __restrict__ Wihb,
                            const float* __restrict__ Whhb, const float* __restrict__ bb) {
    int i = blockIdx.x * blockDim.x + threadIdx.x;
    int stride = gridDim.x * blockDim.x;
    for (int idx = i; idx < EMB * 1024; idx += stride) {
        int e = idx >> 10, c = idx & 1023, d = c >> 9, j = c & 511;
        g_WihT[idx] = (d ? Wihb : Wihf)[j * EMB + e];
    }
    for (int idx = i; idx < 2 * HID * G4; idx += stride) {
        int d = idx >> 16, r = idx & 65535, k = r >> 9, j = r & 511;
        g_WhhT[idx] = (d ? Whhb : Whhf)[j * HID + k];
    }
    for (int idx = i; idx < 1024; idx += stride) {
        int d = idx >> 9, j = idx & 511;
        g_bias[idx] = (d ? bb : bf)[j];
    }
}

// ---------------- vocab projection: proj[v] = emb[v] @ W_ih^T + b (both dirs) ---------
// Tile: 64 vocab rows x 128 cols. Same micro-structure (and thus identical fp32
// accumulation order) as the previous per-position xg kernel -> bit-identical gates.
__global__ void __launch_bounds__(256) proj_kernel(const float* __restrict__ emb) {
    __shared__ float xs[64 * EMB];
    int tid = threadIdx.x;
    int rbase = blockIdx.y * 64;
    int cbase = blockIdx.x * 128;

    for (int i = tid; i < 64 * EMB; i += 256) {
        int r = i / EMB, e = i - r * EMB;
        int row = rbase + r;
        xs[i] = (row < VOCAB) ? emb[row * EMB + e] : 0.f;
    }
    __syncthreads();

    int tx = tid & 31, ty = tid >> 5;
    int c0 = cbase + tx * 4;

    uint64_t accA[8], accB[8];
    uint64_t z = pack2(0.f, 0.f);
#pragma unroll
    for (int i = 0; i < 8; i++) { accA[i] = z; accB[i] = z; }

    const float* xrow = xs + (ty * 8) * EMB;
    for (int e = 0; e < EMB; e++) {
        ulonglong2 w2 = *(const ulonglong2*)&g_WihT[e * 1024 + c0];
#pragma unroll
        for (int i = 0; i < 8; i++) {
            float xv = xrow[i * EMB + e];
            uint64_t xx = pack2(xv, xv);
            ffma2(accA[i], xx, w2.x);
            ffma2(accB[i], xx, w2.y);
        }
    }

    float4 bias = *(const float4*)&g_bias[c0];
#pragma unroll
    for (int i = 0; i < 8; i++) {
        int row = rbase + ty * 8 + i;
        if (row < VOCAB) {
            float2 vA = unpack2(accA[i]);
            float2 vB = unpack2(accB[i]);
            float4 o;
            o.x = vA.x + bias.x; o.y = vA.y + bias.y;
            o.z = vB.x + bias.z; o.w = vB.y + bias.w;
            *(float4*)&g_proj[(size_t)row * 1024 + c0] = o;
        }
    }
}

// ---------------- persistent bidirectional LSTM: 1024 threads, split-k, proj gather ---
// Grid 128: dir = bid&1, 4 batch elements per CTA.
// Thread t: gcol = t&511, half = t>>9 (k-range [half*64, half*64+64)).
// xg for (b, t) is gathered from g_proj[ids[b][t]*1024 + dir*512 + gcol].
// smem: Wc[2*KSM][512] (192KB) + part[2][2048] (16KB) + hbuf[512] (2KB) + ids[2048] (8KB)
extern __shared__ float lsmem[];
__device__ __forceinline__ float sigf(float x) { return 1.f / (1.f + expf(-x)); }

__global__ void __launch_bounds__(1024, 1) lstm_kernel(const int* __restrict__ ids) {
    float* Wc   = lsmem;                       // 2*KSM*512
    float* part = lsmem + 2 * KSM * 512;       // 2*2048
    float* hbuf = part + 4096;                 // 512 (16B aligned)
    int*   sids = (int*)(hbuf + 512);          // 4*512

    int tid   = threadIdx.x;
    int gcol  = tid & 511;
    int half  = tid >> 9;
    int dir   = blockIdx.x & 1;
    int bbase = (blockIdx.x >> 1) * 4;

    const float* Wt = g_WhhT + dir * (HID * G4);

    // cooperative smem load: Wc row r <- global row (r<KSM ? r : r-KSM+64)
    for (int i = tid; i < 2 * KSM * 512; i += 1024) {
        int r = i >> 9, c = i & 511;
        int gr = (r < KSM) ? r : (r - KSM + 64);
        Wc[i] = Wt[gr * 512 + c];
    }
    if (tid < 512) hbuf[tid] = 0.f;
    // stage this CTA's ids: sids[b*512 + t]
    for (int i = tid; i < 4 * Ln; i += 1024) {
        int b = i >> 9, t = i & 511;
        sids[i] = ids[(bbase + b) * Ln + t];
    }

    // register W rows: global rows half*64 + KSM + kk
    float wreg[KRG];
#pragma unroll
    for (int kk = 0; kk < KRG; kk++)
        wreg[kk] = Wt[(half * 64 + KSM + kk) * 512 + gcol];

    float creg = 0.f;
    float* hout = dir ? g_hb : g_hf;
    int dcol = dir * 512 + gcol;               // column within a proj row

    __syncthreads();

    int tt0 = dir ? (Ln - 1) : 0;
    float cxg0 = 0.f, cxg1 = 0.f, cxg2 = 0.f, cxg3 = 0.f;
    if (half == 0) {                            // only half 0 folds xg into its partial
        cxg0 = g_proj[(size_t)sids[tt0]        * 1024 + dcol];
        cxg1 = g_proj[(size_t)sids[512  + tt0] * 1024 + dcol];
        cxg2 = g_proj[(size_t)sids[1024 + tt0] * 1024 + dcol];
        cxg3 = g_proj[(size_t)sids[1536 + tt0] * 1024 + dcol];
    }

    const float*  wp  = Wc + half * (KSM * 512) + gcol;
    const float4* hb4 = (const float4*)hbuf + half * 64;   // this half's k-range
    int b2 = tid & 3, k2 = tid >> 2;                       // phase-2 mapping (tid<512)
    float* partw = part + half * 2048 + gcol * 4;

    for (int s = 0; s < Ln; s++) {
        int tt = dir ? (Ln - 1 - s) : s;
        // prefetch next step's xg (half 0 only; hidden under the dot-product loop)
        float nxg0 = 0.f, nxg1 = 0.f, nxg2 = 0.f, nxg3 = 0.f;
        if (half == 0 && s + 1 < Ln) {
            int tn = dir ? (tt - 1) : (tt + 1);
            nxg0 = g_proj[(size_t)sids[tn]        * 1024 + dcol];
            nxg1 = g_proj[(size_t)sids[512  + tn] * 1024 + dcol];
            nxg2 = g_proj[(size_t)sids[1024 + tn] * 1024 + dcol];
            nxg3 = g_proj[(size_t)sids[1536 + tn] * 1024 + dcol];
        }

        // ---- phase 1: partial gate dot products over this half's 64 k ----
        float a0 = cxg0, a1 = cxg1, a2 = cxg2, a3 = cxg3;
#pragma unroll 8
        for (int kk = 0; kk < KSM; kk++) {
            float4 h4 = hb4[kk];                 // broadcast within warp
            float  w  = wp[kk * 512];
            a0 += h4.x * w; a1 += h4.y * w; a2 += h4.z * w; a3 += h4.w * w;
        }
#pragma unroll
        for (int kk = 0; kk < KRG; kk++) {
            float4 h4 = hb4[KSM + kk];
            float  w  = wreg[kk];
            a0 += h4.x * w; a1 += h4.y * w; a2 += h4.z * w; a3 += h4.w * w;
        }
        float4 pv; pv.x = a0; pv.y = a1; pv.z = a2; pv.w = a3;
        *(float4*)partw = pv;                     // conflict-free STS.128
        __syncthreads();

        // ---- phase 2: combine halves + cell update for (b2, k2) ----
        if (tid < 512) {
            float gi = part[k2 * 4 + b2]           + part[2048 + k2 * 4 + b2];
            float gf = part[512  + k2 * 4 + b2]    + part[2560 + k2 * 4 + b2];
            float gg = part[1024 + k2 * 4 + b2]    + part[3072 + k2 * 4 + b2];
            float go = part[1536 + k2 * 4 + b2]    + part[3584 + k2 * 4 + b2];
            creg = sigf(gf) * creg + sigf(gi) * tanhf(gg);
            float h = sigf(go) * tanhf(creg);
            hbuf[tid] = h;                         // hbuf[k2*4 + b2] == hbuf[tid]
            hout[((bbase + b2) * Ln + tt) * HID + k2] = h;
        }
        __syncthreads();

        cxg0 = nxg0; cxg1 = nxg1; cxg2 = nxg2; cxg3 = nxg3;
    }
}

// ---------------- FC: emissions = [h_f, h_b] @ fc_W^T + fc_b ----------------
__global__ void __launch_bounds__(256) fc_kernel(const float* __restrict__ fcW,
                                                 const float* __restrict__ fcb) {
    int warp = (blockIdx.x * blockDim.x + threadIdx.x) >> 5;
    int lane = threadIdx.x & 31;
    if (warp >= BL) return;
    float4 hf = *(const float4*)&g_hf[warp * HID + lane * 4];
    float4 hb = *(const float4*)&g_hb[warp * HID + lane * 4];
#pragma unroll
    for (int t = 0; t < TAGS; t++) {
        float4 wf = *(const float4*)&fcW[t * 256 + lane * 4];
        float4 wb = *(const float4*)&fcW[t * 256 + 128 + lane * 4];
        float s = hf.x * wf.x + hf.y * wf.y + hf.z * wf.z + hf.w * wf.w
                + hb.x * wb.x + hb.y * wb.y + hb.z * wb.z + hb.w * wb.w;
#pragma unroll
        for (int off = 16; off; off >>= 1) s += __shfl_xor_sync(0xffffffffu, s, off);
        if (lane == 0) g_em[warp * TAGS + t] = s + fcb[t];
    }
}

// ---------------- Viterbi: one warp per batch element; float32 output ----------------
__global__ void __launch_bounds__(128) viterbi_kernel(const int* __restrict__ ids,
                                                      const float* __restrict__ trans,
                                                      const float* __restrict__ start_t,
                                                      const float* __restrict__ end_t,
                                                      float* __restrict__ out) {
    __shared__ unsigned char hist[4][Ln * 20];
    int w = threadIdx.x >> 5, lane = threadIdx.x & 31;
    int b = blockIdx.x * 4 + w;
    const float NEG = -3e38f;

    float tcol[TAGS];
#pragma unroll
    for (int i = 0; i < TAGS; i++)
        tcol[i] = (lane < TAGS) ? trans[i * TAGS + lane] : 0.f;

    const float* emrow = g_em + b * Ln * TAGS;
    const int*   idrow = ids + b * Ln;

    float score = (lane < TAGS) ? start_t[lane] + emrow[lane] : NEG;

    for (int t = 1; t < Ln; t++) {
        float em = (lane < TAGS) ? emrow[t * TAGS + lane] : 0.f;
        int mask = (idrow[t] != 0);
        float best = NEG; int bi = 0;
#pragma unroll
        for (int i = 0; i < TAGS; i++) {
            float si = __shfl_sync(0xffffffffu, score, i);
            float v = si + tcol[i];
            if (v > best) { best = v; bi = i; }   // first max wins (matches jnp.argmax)
        }
        int idx;
        if (mask) { if (lane < TAGS) score = best + em; idx = bi; }
        else      { idx = lane; }                  // identity backpointer on pads
        if (lane < TAGS) hist[w][t * 20 + lane] = (unsigned char)idx;
    }

    float fin = (lane < TAGS) ? score + end_t[lane] : NEG;
    int fid = lane;
#pragma unroll
    for (int off = 16; off; off >>= 1) {
        float ov = __shfl_xor_sync(0xffffffffu, fin, off);
        int   oi = __shfl_xor_sync(0xffffffffu, fid, off);
        if (ov > fin || (ov == fin && oi < fid)) { fin = ov; fid = oi; }
    }
    __syncwarp();

    if (lane == 0) {
        int tag = fid;
        float* orow = out + b * Ln;
        orow[Ln - 1] = (idrow[Ln - 1] != 0) ? (float)tag : 0.f;
        for (int t = Ln - 2; t >= 0; t--) {
            tag = hist[w][(t + 1) * 20 + tag];
            orow[t] = (idrow[t] != 0) ? (float)tag : 0.f;
        }
    }
}

// ---------------- launch ----------------
extern "C" void kernel_launch(void* const* d_in, const int* in_sizes, int n_in,
                              void* d_out, int out_size) {
    const void* p[13];
    for (int i = 0; i < 13; i++) p[i] = 0;
    int c51200 = 0, c65536 = 0, c512 = 0, c17 = 0;
    for (int i = 0; i < n_in; i++) {
        switch (in_sizes[i]) {
            case 131072:  p[0] = d_in[i]; break;
            case 3000000: p[1] = d_in[i]; break;
            case 51200:   p[(c51200++ == 0) ? 2 : 5] = d_in[i]; break;
            case 65536:   p[(c65536++ == 0) ? 3 : 6] = d_in[i]; break;
            case 512:     p[(c512++   == 0) ? 4 : 7] = d_in[i]; break;
            case 4352:    p[8]  = d_in[i]; break;
            case 289:     p[10] = d_in[i]; break;
            case 17: {
                int k = c17++;
                p[(k == 0) ? 9 : ((k == 1) ? 11 : 12)] = d_in[i];
                break;
            }
            default: break;
        }
    }
    const int*   input_ids = (const int*)  p[0];
    const float* emb       = (const float*)p[1];
    const float* Wihf      = (const float*)p[2];
    const float* Whhf      = (const float*)p[3];
    const float* bf        = (const float*)p[4];
    const float* Wihb      = (const float*)p[5];
    const float* Whhb      = (const float*)p[6];
    const float* bb        = (const float*)p[7];
    const float* fcW       = (const float*)p[8];
    const float* fcb       = (const float*)p[9];
    const float* trans     = (const float*)p[10];
    const float* startt    = (const float*)p[11];
    const float* endt      = (const float*)p[12];
    float* out = (float*)d_out;

    prep_kernel<<<64, 256>>>(Wihf, Whhf, bf, Wihb, Whhb, bb);
    proj_kernel<<<dim3(8, (VOCAB + 63) / 64), 256>>>(emb);   // 469 row-tiles

    const int lsmem_bytes = (2 * KSM * 512 + 4096 + 512 + 2048) * (int)sizeof(float); // 223232
    cudaFuncSetAttribute(lstm_kernel, cudaFuncAttributeMaxDynamicSharedMemorySize,
                         lsmem_bytes);
    lstm_kernel<<<128, 1024, lsmem_bytes>>>(input_ids);

    fc_kernel<<<16384, 256>>>(fcW, fcb);
    viterbi_kernel<<<64, 128>>>(input_ids, trans, startt, endt, out);
}

// round 10
// speedup vs baseline: 1.5367x; 1.0150x over previous
#include <cuda_runtime.h>
#include <math.h>
#include <stdint.h>

#define Bn   256
#define Ln   512
#define VOCAB 30000
#define EMB  100
#define HID  128
#define G4   512          // 4*HID
#define TAGS 17
#define BL   (Bn*Ln)      // 131072
#define KSM  48           // smem W rows per k-half
#define KRG  16           // register W rows per k-half

// ---------------- scratch (device globals: allocation-free, per rules) ----------------
__device__ float g_proj[VOCAB * 1024];  // 123MB: per-vocab gate preactivations, both dirs
__device__ float g_hf[BL * HID];        // forward hidden states
__device__ float g_hb[BL * HID];        // backward hidden states
__device__ float g_em[BL * TAGS];       // emissions
__device__ float g_WihT[EMB * 1024];    // W_ih transposed, dirs concatenated on cols
__device__ float g_WhhT[2 * HID * G4];  // W_hh transposed (k-major), per dir
__device__ float g_bias[1024];          // b_f ++ b_b
__device__ int   g_dummy;

// ---------------- packed f32x2 helpers ----------------
__device__ __forceinline__ uint64_t pack2(float lo, float hi) {
    uint64_t r;
    asm("mov.b64 %0, {%1, %2};" : "=l"(r) : "f"(lo), "f"(hi));
    return r;
}
__device__ __forceinline__ float2 unpack2(uint64_t v) {
    float lo, hi;
    asm("mov.b64 {%0, %1}, %2;" : "=f"(lo), "=f"(hi) : "l"(v));
    return make_float2(lo, hi);
}
__device__ __forceinline__ void ffma2(uint64_t& acc, uint64_t a, uint64_t b) {
    asm("fma.rn.f32x2 %0, %1, %2, %0;" : "+l"(acc) : "l"(a), "l"(b));
}

// ---------------- filler (makes lstm_kernel the 4th launch for ncu capture) ----------
__global__ void filler_kernel() { if (threadIdx.x == 1024) g_dummy = 1; }

// ---------------- prep: transpose weights ----------------
__global__ void prep_kernel(const float* __restrict__ Wihf, const float* __restrict__ Whhf,
                            const float* __restrict__ bf,   const float* __restrict__ Wihb,
                            const float* __restrict__ Whhb, const float* __restrict__ bb) {
    int i = blockIdx.x * blockDim.x + threadIdx.x;
    int stride = gridDim.x * blockDim.x;
    for (int idx = i; idx < EMB * 1024; idx += stride) {
        int e = idx >> 10, c = idx & 1023, d = c >> 9, j = c & 511;
        g_WihT[idx] = (d ? Wihb : Wihf)[j * EMB + e];
    }
    for (int idx = i; idx < 2 * HID * G4; idx += stride) {
        int d = idx >> 16, r = idx & 65535, k = r >> 9, j = r & 511;
        g_WhhT[idx] = (d ? Whhb : Whhf)[j * HID + k];
    }
    for (int idx = i; idx < 1024; idx += stride) {
        int d = idx >> 9, j = idx & 511;
        g_bias[idx] = (d ? bb : bf)[j];
    }
}

// ---------------- vocab projection: proj[v] = emb[v] @ W_ih^T + b (both dirs) ---------
__global__ void __launch_bounds__(256) proj_kernel(const float* __restrict__ emb) {
    __shared__ float xs[64 * EMB];
    int tid = threadIdx.x;
    int rbase = blockIdx.y * 64;
    int cbase = blockIdx.x * 128;

    for (int i = tid; i < 64 * EMB; i += 256) {
        int r = i / EMB, e = i - r * EMB;
        int row = rbase + r;
        xs[i] = (row < VOCAB) ? emb[row * EMB + e] : 0.f;
    }
    __syncthreads();

    int tx = tid & 31, ty = tid >> 5;
    int c0 = cbase + tx * 4;

    uint64_t accA[8], accB[8];
    uint64_t z = pack2(0.f, 0.f);
#pragma unroll
    for (int i = 0; i < 8; i++) { accA[i] = z; accB[i] = z; }

    const float* xrow = xs + (ty * 8) * EMB;
    for (int e = 0; e < EMB; e++) {
        ulonglong2 w2 = *(const ulonglong2*)&g_WihT[e * 1024 + c0];
#pragma unroll
        for (int i = 0; i < 8; i++) {
            float xv = xrow[i * EMB + e];
            uint64_t xx = pack2(xv, xv);
            ffma2(accA[i], xx, w2.x);
            ffma2(accB[i], xx, w2.y);
        }
    }

    float4 bias = *(const float4*)&g_bias[c0];
#pragma unroll
    for (int i = 0; i < 8; i++) {
        int row = rbase + ty * 8 + i;
        if (row < VOCAB) {
            float2 vA = unpack2(accA[i]);
            float2 vB = unpack2(accB[i]);
            float4 o;
            o.x = vA.x + bias.x; o.y = vA.y + bias.y;
            o.z = vB.x + bias.z; o.w = vB.y + bias.w;
            *(float4*)&g_proj[(size_t)row * 1024 + c0] = o;
        }
    }
}

// ---------------- persistent bidirectional LSTM: 1024 threads, split-k, proj gather ---
extern __shared__ float lsmem[];
__device__ __forceinline__ float sigf(float x) { return 1.f / (1.f + expf(-x)); }

__global__ void __launch_bounds__(1024, 1) lstm_kernel(const int* __restrict__ ids) {
    float* Wc   = lsmem;                       // 2*KSM*512
    float* part = lsmem + 2 * KSM * 512;       // 2*2048
    float* hbuf = part + 4096;                 // 512 (16B aligned)
    int*   sids = (int*)(hbuf + 512);          // 4*512

    int tid   = threadIdx.x;
    int gcol  = tid & 511;
    int half  = tid >> 9;
    int dir   = blockIdx.x & 1;
    int bbase = (blockIdx.x >> 1) * 4;

    const float* Wt = g_WhhT + dir * (HID * G4);

    for (int i = tid; i < 2 * KSM * 512; i += 1024) {
        int r = i >> 9, c = i & 511;
        int gr = (r < KSM) ? r : (r - KSM + 64);
        Wc[i] = Wt[gr * 512 + c];
    }
    if (tid < 512) hbuf[tid] = 0.f;
    for (int i = tid; i < 4 * Ln; i += 1024) {
        int b = i >> 9, t = i & 511;
        sids[i] = ids[(bbase + b) * Ln + t];
    }

    float wreg[KRG];
#pragma unroll
    for (int kk = 0; kk < KRG; kk++)
        wreg[kk] = Wt[(half * 64 + KSM + kk) * 512 + gcol];

    float creg = 0.f;
    float* hout = dir ? g_hb : g_hf;
    int dcol = dir * 512 + gcol;

    __syncthreads();

    int tt0 = dir ? (Ln - 1) : 0;
    float cxg0 = 0.f, cxg1 = 0.f, cxg2 = 0.f, cxg3 = 0.f;
    if (half == 0) {
        cxg0 = g_proj[(size_t)sids[tt0]        * 1024 + dcol];
        cxg1 = g_proj[(size_t)sids[512  + tt0] * 1024 + dcol];
        cxg2 = g_proj[(size_t)sids[1024 + tt0] * 1024 + dcol];
        cxg3 = g_proj[(size_t)sids[1536 + tt0] * 1024 + dcol];
    }

    const float*  wp  = Wc + half * (KSM * 512) + gcol;
    const float4* hb4 = (const float4*)hbuf + half * 64;
    int b2 = tid & 3, k2 = tid >> 2;
    float* partw = part + half * 2048 + gcol * 4;

    for (int s = 0; s < Ln; s++) {
        int tt = dir ? (Ln - 1 - s) : s;
        float nxg0 = 0.f, nxg1 = 0.f, nxg2 = 0.f, nxg3 = 0.f;
        if (half == 0 && s + 1 < Ln) {
            int tn = dir ? (tt - 1) : (tt + 1);
            nxg0 = g_proj[(size_t)sids[tn]        * 1024 + dcol];
            nxg1 = g_proj[(size_t)sids[512  + tn] * 1024 + dcol];
            nxg2 = g_proj[(size_t)sids[1024 + tn] * 1024 + dcol];
            nxg3 = g_proj[(size_t)sids[1536 + tn] * 1024 + dcol];
        }

        float a0 = cxg0, a1 = cxg1, a2 = cxg2, a3 = cxg3;
#pragma unroll 8
        for (int kk = 0; kk < KSM; kk++) {
            float4 h4 = hb4[kk];
            float  w  = wp[kk * 512];
            a0 += h4.x * w; a1 += h4.y * w; a2 += h4.z * w; a3 += h4.w * w;
        }
#pragma unroll
        for (int kk = 0; kk < KRG; kk++) {
            float4 h4 = hb4[KSM + kk];
            float  w  = wreg[kk];
            a0 += h4.x * w; a1 += h4.y * w; a2 += h4.z * w; a3 += h4.w * w;
        }
        float4 pv; pv.x = a0; pv.y = a1; pv.z = a2; pv.w = a3;
        *(float4*)partw = pv;
        __syncthreads();

        if (tid < 512) {
            float gi = part[k2 * 4 + b2]           + part[2048 + k2 * 4 + b2];
            float gf = part[512  + k2 * 4 + b2]    + part[2560 + k2 * 4 + b2];
            float gg = part[1024 + k2 * 4 + b2]    + part[3072 + k2 * 4 + b2];
            float go = part[1536 + k2 * 4 + b2]    + part[3584 + k2 * 4 + b2];
            creg = sigf(gf) * creg + sigf(gi) * tanhf(gg);
            float h = sigf(go) * tanhf(creg);
            hbuf[tid] = h;
            hout[((bbase + b2) * Ln + tt) * HID + k2] = h;
        }
        __syncthreads();

        cxg0 = nxg0; cxg1 = nxg1; cxg2 = nxg2; cxg3 = nxg3;
    }
}

// ---------------- FC: emissions = [h_f, h_b] @ fc_W^T + fc_b ----------------
// Block 256 = 8 warps; warp handles 4 positions; 8 lanes per position (sl = lane&7),
// each lane owns 32 h-values in registers; fcW staged in smem, read as broadcast
// LDS.128; 3-stage shfl_xor reduce within the 8-lane group.
__global__ void __launch_bounds__(256) fc_kernel(const float* __restrict__ fcW,
                                                 const float* __restrict__ fcb) {
    __shared__ float wsm[TAGS * 256];
    __shared__ float fcb_s[TAGS];
    int tid = threadIdx.x;
    for (int i = tid; i < TAGS * 256; i += 256) wsm[i] = fcW[i];
    if (tid < TAGS) fcb_s[tid] = fcb[tid];
    __syncthreads();

    int lane = tid & 31, warp = tid >> 5;
    int pw = lane >> 3, sl = lane & 7;
    int pos = blockIdx.x * 32 + warp * 4 + pw;

    // load this lane's interleaved h slice: chunk c = i*8+sl (i=0..3 -> hf, 4..7 -> hb)
    float4 h4[8];
    const float4* hfp = (const float4*)(g_hf + (size_t)pos * HID);
    const float4* hbp = (const float4*)(g_hb + (size_t)pos * HID);
#pragma unroll
    for (int i = 0; i < 4; i++) h4[i]     = hfp[i * 8 + sl];
#pragma unroll
    for (int i = 0; i < 4; i++) h4[4 + i] = hbp[i * 8 + sl];

    const float4* w4 = (const float4*)wsm;
    float* emrow = g_em + (size_t)pos * TAGS;
#pragma unroll
    for (int t = 0; t < TAGS; t++) {
        float s = 0.f;
#pragma unroll
        for (int i = 0; i < 8; i++) {
            float4 w = w4[t * 64 + i * 8 + sl];
            s += h4[i].x * w.x + h4[i].y * w.y + h4[i].z * w.z + h4[i].w * w.w;
        }
        s += __shfl_xor_sync(0xffffffffu, s, 1);
        s += __shfl_xor_sync(0xffffffffu, s, 2);
        s += __shfl_xor_sync(0xffffffffu, s, 4);
        if (sl == 0) emrow[t] = s + fcb_s[t];
    }
}

// ---------------- Viterbi: one warp per batch element; float32 output ----------------
__global__ void __launch_bounds__(128) viterbi_kernel(const int* __restrict__ ids,
                                                      const float* __restrict__ trans,
                                                      const float* __restrict__ start_t,
                                                      const float* __restrict__ end_t,
                                                      float* __restrict__ out) {
    __shared__ unsigned char hist[4][Ln * 20];
    int w = threadIdx.x >> 5, lane = threadIdx.x & 31;
    int b = blockIdx.x * 4 + w;
    const float NEG = -3e38f;

    float tcol[TAGS];
#pragma unroll
    for (int i = 0; i < TAGS; i++)
        tcol[i] = (lane < TAGS) ? trans[i * TAGS + lane] : 0.f;

    const float* emrow = g_em + b * Ln * TAGS;
    const int*   idrow = ids + b * Ln;

    float score = (lane < TAGS) ? start_t[lane] + emrow[lane] : NEG;

    for (int t = 1; t < Ln; t++) {
        float em = (lane < TAGS) ? emrow[t * TAGS + lane] : 0.f;
        int mask = (idrow[t] != 0);
        float best = NEG; int bi = 0;
#pragma unroll
        for (int i = 0; i < TAGS; i++) {
            float si = __shfl_sync(0xffffffffu, score, i);
            float v = si + tcol[i];
            if (v > best) { best = v; bi = i; }
        }
        int idx;
        if (mask) { if (lane < TAGS) score = best + em; idx = bi; }
        else      { idx = lane; }
        if (lane < TAGS) hist[w][t * 20 + lane] = (unsigned char)idx;
    }

    float fin = (lane < TAGS) ? score + end_t[lane] : NEG;
    int fid = lane;
#pragma unroll
    for (int off = 16; off; off >>= 1) {
        float ov = __shfl_xor_sync(0xffffffffu, fin, off);
        int   oi = __shfl_xor_sync(0xffffffffu, fid, off);
        if (ov > fin || (ov == fin && oi < fid)) { fin = ov; fid = oi; }
    }
    __syncwarp();

    if (lane == 0) {
        int tag = fid;
        float* orow = out + b * Ln;
        orow[Ln - 1] = (idrow[Ln - 1] != 0) ? (float)tag : 0.f;
        for (int t = Ln - 2; t >= 0; t--) {
            tag = hist[w][(t + 1) * 20 + tag];
            orow[t] = (idrow[t] != 0) ? (float)tag : 0.f;
        }
    }
}

// ---------------- launch ----------------
extern "C" void kernel_launch(void* const* d_in, const int* in_sizes, int n_in,
                              void* d_out, int out_size) {
    const void* p[13];
    for (int i = 0; i < 13; i++) p[i] = 0;
    int c51200 = 0, c65536 = 0, c512 = 0, c17 = 0;
    for (int i = 0; i < n_in; i++) {
        switch (in_sizes[i]) {
            case 131072:  p[0] = d_in[i]; break;
            case 3000000: p[1] = d_in[i]; break;
            case 51200:   p[(c51200++ == 0) ? 2 : 5] = d_in[i]; break;
            case 65536:   p[(c65536++ == 0) ? 3 : 6] = d_in[i]; break;
            case 512:     p[(c512++   == 0) ? 4 : 7] = d_in[i]; break;
            case 4352:    p[8]  = d_in[i]; break;
            case 289:     p[10] = d_in[i]; break;
            case 17: {
                int k = c17++;
                p[(k == 0) ? 9 : ((k == 1) ? 11 : 12)] = d_in[i];
                break;
            }
            default: break;
        }
    }
    const int*   input_ids = (const int*)  p[0];
    const float* emb       = (const float*)p[1];
    const float* Wihf      = (const float*)p[2];
    const float* Whhf      = (const float*)p[3];
    const float* bf        = (const float*)p[4];
    const float* Wihb      = (const float*)p[5];
    const float* Whhb      = (const float*)p[6];
    const float* bb        = (const float*)p[7];
    const float* fcW       = (const float*)p[8];
    const float* fcb       = (const float*)p[9];
    const float* trans     = (const float*)p[10];
    const float* startt    = (const float*)p[11];
    const float* endt      = (const float*)p[12];
    float* out = (float*)d_out;

    prep_kernel<<<64, 256>>>(Wihf, Whhf, bf, Wihb, Whhb, bb);          // launch 1
    proj_kernel<<<dim3(8, (VOCAB + 63) / 64), 256>>>(emb);             // launch 2
    filler_kernel<<<1, 32>>>();                                        // launch 3

    const int lsmem_bytes = (2 * KSM * 512 + 4096 + 512 + 2048) * (int)sizeof(float);
    cudaFuncSetAttribute(lstm_kernel, cudaFuncAttributeMaxDynamicSharedMemorySize,
                         lsmem_bytes);
    lstm_kernel<<<128, 1024, lsmem_bytes>>>(input_ids);                // launch 4 (ncu)

    fc_kernel<<<4096, 256>>>(fcW, fcb);                                // launch 5
    viterbi_kernel<<<64, 128>>>(input_ids, trans, startt, endt, out);  // launch 6
}

// round 11
// speedup vs baseline: 1.8992x; 1.2359x over previous
#include <cuda_runtime.h>
#include <math.h>
#include <stdint.h>

#define Bn   256
#define Ln   512
#define VOCAB 30000
#define EMB  100
#define HID  128
#define G4   512          // 4*HID
#define TAGS 17
#define BL   (Bn*Ln)      // 131072
#define KSM  40           // smem W rows per k-half
#define KRG  24           // register W rows per k-half (x2 gate-cols = 48 regs)

// ---------------- scratch (device globals: allocation-free, per rules) ----------------
__device__ float g_proj[VOCAB * 1024];  // per-vocab gate preactivations, both dirs
__device__ float g_hf[BL * HID];        // forward hidden states
__device__ float g_hb[BL * HID];        // backward hidden states
__device__ float g_em[BL * TAGS];       // emissions
__device__ float g_WihT[EMB * 1024];    // W_ih transposed, dirs concatenated on cols
__device__ float g_WhhT[2 * HID * G4];  // W_hh transposed (k-major), per dir
__device__ float g_bias[1024];          // b_f ++ b_b
__device__ int   g_dummy;

// ---------------- packed f32x2 helpers ----------------
__device__ __forceinline__ uint64_t pack2(float lo, float hi) {
    uint64_t r;
    asm("mov.b64 %0, {%1, %2};" : "=l"(r) : "f"(lo), "f"(hi));
    return r;
}
__device__ __forceinline__ float2 unpack2(uint64_t v) {
    float lo, hi;
    asm("mov.b64 {%0, %1}, %2;" : "=f"(lo), "=f"(hi) : "l"(v));
    return make_float2(lo, hi);
}
__device__ __forceinline__ void ffma2(uint64_t& acc, uint64_t a, uint64_t b) {
    asm("fma.rn.f32x2 %0, %1, %2, %0;" : "+l"(acc) : "l"(a), "l"(b));
}

// ---------------- filler (keeps lstm_kernel as the 4th launch for ncu capture) -------
__global__ void filler_kernel() { if (threadIdx.x == 1024) g_dummy = 1; }

// ---------------- prep: transpose weights ----------------
__global__ void prep_kernel(const float* __restrict__ Wihf, const float* __restrict__ Whhf,
                            const float* __restrict__ bf,   const float* __restrict__ Wihb,
                            const float* __restrict__ Whhb, const float* __restrict__ bb) {
    int i = blockIdx.x * blockDim.x + threadIdx.x;
    int stride = gridDim.x * blockDim.x;
    for (int idx = i; idx < EMB * 1024; idx += stride) {
        int e = idx >> 10, c = idx & 1023, d = c >> 9, j = c & 511;
        g_WihT[idx] = (d ? Wihb : Wihf)[j * EMB + e];
    }
    for (int idx = i; idx < 2 * HID * G4; idx += stride) {
        int d = idx >> 16, r = idx & 65535, k = r >> 9, j = r & 511;
        g_WhhT[idx] = (d ? Whhb : Whhf)[j * HID + k];
    }
    for (int idx = i; idx < 1024; idx += stride) {
        int d = idx >> 9, j = idx & 511;
        g_bias[idx] = (d ? bb : bf)[j];
    }
}

// ---------------- vocab projection: proj[v] = emb[v] @ W_ih^T + b (both dirs) ---------
__global__ void __launch_bounds__(256) proj_kernel(const float* __restrict__ emb) {
    __shared__ float xs[64 * EMB];
    int tid = threadIdx.x;
    int rbase = blockIdx.y * 64;
    int cbase = blockIdx.x * 128;

    for (int i = tid; i < 64 * EMB; i += 256) {
        int r = i / EMB, e = i - r * EMB;
        int row = rbase + r;
        xs[i] = (row < VOCAB) ? emb[row * EMB + e] : 0.f;
    }
    __syncthreads();

    int tx = tid & 31, ty = tid >> 5;
    int c0 = cbase + tx * 4;

    uint64_t accA[8], accB[8];
    uint64_t z = pack2(0.f, 0.f);
#pragma unroll
    for (int i = 0; i < 8; i++) { accA[i] = z; accB[i] = z; }

    const float* xrow = xs + (ty * 8) * EMB;
    for (int e = 0; e < EMB; e++) {
        ulonglong2 w2 = *(const ulonglong2*)&g_WihT[e * 1024 + c0];
#pragma unroll
        for (int i = 0; i < 8; i++) {
            float xv = xrow[i * EMB + e];
            uint64_t xx = pack2(xv, xv);
            ffma2(accA[i], xx, w2.x);
            ffma2(accB[i], xx, w2.y);
        }
    }

    float4 bias = *(const float4*)&g_bias[c0];
#pragma unroll
    for (int i = 0; i < 8; i++) {
        int row = rbase + ty * 8 + i;
        if (row < VOCAB) {
            float2 vA = unpack2(accA[i]);
            float2 vB = unpack2(accB[i]);
            float4 o;
            o.x = vA.x + bias.x; o.y = vA.y + bias.y;
            o.z = vB.x + bias.z; o.w = vB.y + bias.w;
            *(float4*)&g_proj[(size_t)row * 1024 + c0] = o;
        }
    }
}

// ---------------- persistent bidirectional LSTM: 512 threads, 8 acc/thread ----------
// Grid 128: dir = bid&1, 4 batch elements per CTA.
// Thread t: half = t>>8 (k-range [half*64, half*64+64)), gate-col pair g0 = 2*(t&255).
// 8 accumulators = 2 gate-cols x 4 batches: each 16B h-broadcast feeds 8 FMAs,
// each W access is an LDS.64 feeding 8 FMAs. 48 W values per thread in registers.
// Numerics identical to the previous split-k-2 kernel (same half grouping, same
// kk-ascending order, xg folded into half 0).
extern __shared__ float lsmem[];
__device__ __forceinline__ float sigf(float x) { return 1.f / (1.f + expf(-x)); }

__global__ void __launch_bounds__(512, 1) lstm_kernel(const int* __restrict__ ids) {
    float* Wc   = lsmem;                       // 2*KSM*512 floats
    float* part = lsmem + 2 * KSM * 512;       // 4096 floats: [half][gcol][b]
    float* hbuf = part + 4096;                 // 512 floats  [k][b] (16B aligned)
    int*   sids = (int*)(hbuf + 512);          // 2048 ints (pre-scaled id*1024)

    int tid   = threadIdx.x;
    int half  = tid >> 8;                      // k-half
    int g0    = (tid & 255) * 2;               // first of 2 gate columns
    int dir   = blockIdx.x & 1;
    int bbase = (blockIdx.x >> 1) * 4;

    const float* Wt = g_WhhT + dir * (HID * G4);

    // cooperative smem W load: Wc[h][r][c] <- global row h*64 + r  (r < KSM)
    for (int i = tid; i < 2 * KSM * 512; i += 512) {
        int hh = i / (KSM * 512);
        int rem = i - hh * (KSM * 512);
        int r = rem >> 9, c = rem & 511;
        Wc[i] = Wt[(hh * 64 + r) * 512 + c];
    }
    hbuf[tid] = 0.f;
    for (int i = tid; i < 4 * Ln; i += 512) {
        int b = i >> 9, t = i & 511;
        sids[i] = ids[(bbase + b) * Ln + t] * 1024;   // pre-scaled row offset
    }

    // register W rows: global rows half*64 + KSM + j, both gate columns
    float wregA[KRG], wregB[KRG];
#pragma unroll
    for (int j = 0; j < KRG; j++) {
        wregA[j] = Wt[(half * 64 + KSM + j) * 512 + g0];
        wregB[j] = Wt[(half * 64 + KSM + j) * 512 + g0 + 1];
    }

    float creg = 0.f;
    float* hout = dir ? g_hb : g_hf;
    int dcol = dir * 512 + g0;

    __syncthreads();

    int tt0 = dir ? (Ln - 1) : 0;
    float cxA[4], cxB[4], nxA[4], nxB[4];
#pragma unroll
    for (int b = 0; b < 4; b++) { cxA[b] = 0.f; cxB[b] = 0.f; }
    if (half == 0) {
#pragma unroll
        for (int b = 0; b < 4; b++) {
            float2 v = *(const float2*)&g_proj[sids[b * 512 + tt0] + dcol];
            cxA[b] = v.x; cxB[b] = v.y;
        }
    }

    const float*  wp  = Wc + half * (KSM * 512) + g0;
    const float4* hb4 = (const float4*)hbuf + half * 64;   // this half's k-range
    int b2 = tid & 3, k2 = tid >> 2;                       // phase-2 mapping
    float* partw = part + half * 2048 + g0 * 4;

    for (int s = 0; s < Ln; s++) {
        int tt = dir ? (Ln - 1 - s) : s;
        // prefetch next step's xg (half 0; hidden under the dot-product loop)
#pragma unroll
        for (int b = 0; b < 4; b++) { nxA[b] = 0.f; nxB[b] = 0.f; }
        if (half == 0 && s + 1 < Ln) {
            int tn = dir ? (tt - 1) : (tt + 1);
#pragma unroll
            for (int b = 0; b < 4; b++) {
                float2 v = *(const float2*)&g_proj[sids[b * 512 + tn] + dcol];
                nxA[b] = v.x; nxB[b] = v.y;
            }
        }

        // ---- phase 1: partial gate dot products (2 gate-cols x 4 batches) ----
        float aA0 = cxA[0], aA1 = cxA[1], aA2 = cxA[2], aA3 = cxA[3];
        float aB0 = cxB[0], aB1 = cxB[1], aB2 = cxB[2], aB3 = cxB[3];
#pragma unroll 8
        for (int r = 0; r < KSM; r++) {
            float4 h4 = hb4[r];                       // 16B broadcast: feeds 8 FMAs
            float2 w2 = *(const float2*)(wp + r * 512);
            aA0 += h4.x * w2.x; aA1 += h4.y * w2.x; aA2 += h4.z * w2.x; aA3 += h4.w * w2.x;
            aB0 += h4.x * w2.y; aB1 += h4.y * w2.y; aB2 += h4.z * w2.y; aB3 += h4.w * w2.y;
        }
#pragma unroll
        for (int j = 0; j < KRG; j++) {
            float4 h4 = hb4[KSM + j];
            float  wa = wregA[j], wb = wregB[j];
            aA0 += h4.x * wa; aA1 += h4.y * wa; aA2 += h4.z * wa; aA3 += h4.w * wa;
            aB0 += h4.x * wb; aB1 += h4.y * wb; aB2 += h4.z * wb; aB3 += h4.w * wb;
        }
        float4 pvA; pvA.x = aA0; pvA.y = aA1; pvA.z = aA2; pvA.w = aA3;
        float4 pvB; pvB.x = aB0; pvB.y = aB1; pvB.z = aB2; pvB.w = aB3;
        *(float4*)partw       = pvA;               // part[half][g0][0..3]
        *(float4*)(partw + 4) = pvB;               // part[half][g0+1][0..3]
        __syncthreads();

        // ---- phase 2: combine halves + cell update, all 512 threads ----
        {
            float gi = part[k2 * 4 + b2]          + part[2048 + k2 * 4 + b2];
            float gf = part[512  + k2 * 4 + b2]   + part[2560 + k2 * 4 + b2];
            float gg = part[1024 + k2 * 4 + b2]   + part[3072 + k2 * 4 + b2];
            float go = part[1536 + k2 * 4 + b2]   + part[3584 + k2 * 4 + b2];
            creg = sigf(gf) * creg + sigf(gi) * tanhf(gg);
            float h = sigf(go) * tanhf(creg);
            hbuf[tid] = h;                         // hbuf[k2*4 + b2] == hbuf[tid]
            hout[((bbase + b2) * Ln + tt) * HID + k2] = h;
        }
        __syncthreads();

#pragma unroll
        for (int b = 0; b < 4; b++) { cxA[b] = nxA[b]; cxB[b] = nxB[b]; }
    }
}

// ---------------- FC: emissions = [h_f, h_b] @ fc_W^T + fc_b ----------------
__global__ void __launch_bounds__(256) fc_kernel(const float* __restrict__ fcW,
                                                 const float* __restrict__ fcb) {
    __shared__ float wsm[TAGS * 256];
    __shared__ float fcb_s[TAGS];
    int tid = threadIdx.x;
    for (int i = tid; i < TAGS * 256; i += 256) wsm[i] = fcW[i];
    if (tid < TAGS) fcb_s[tid] = fcb[tid];
    __syncthreads();

    int lane = tid & 31, warp = tid >> 5;
    int pw = lane >> 3, sl = lane & 7;
    int pos = blockIdx.x * 32 + warp * 4 + pw;

    float4 h4[8];
    const float4* hfp = (const float4*)(g_hf + (size_t)pos * HID);
    const float4* hbp = (const float4*)(g_hb + (size_t)pos * HID);
#pragma unroll
    for (int i = 0; i < 4; i++) h4[i]     = hfp[i * 8 + sl];
#pragma unroll
    for (int i = 0; i < 4; i++) h4[4 + i] = hbp[i * 8 + sl];

    const float4* w4 = (const float4*)wsm;
    float* emrow = g_em + (size_t)pos * TAGS;
#pragma unroll
    for (int t = 0; t < TAGS; t++) {
        float s = 0.f;
#pragma unroll
        for (int i = 0; i < 8; i++) {
            float4 w = w4[t * 64 + i * 8 + sl];
            s += h4[i].x * w.x + h4[i].y * w.y + h4[i].z * w.z + h4[i].w * w.w;
        }
        s += __shfl_xor_sync(0xffffffffu, s, 1);
        s += __shfl_xor_sync(0xffffffffu, s, 2);
        s += __shfl_xor_sync(0xffffffffu, s, 4);
        if (sl == 0) emrow[t] = s + fcb_s[t];
    }
}

// ---------------- Viterbi: one warp per batch element; float32 output ----------------
__global__ void __launch_bounds__(128) viterbi_kernel(const int* __restrict__ ids,
                                                      const float* __restrict__ trans,
                                                      const float* __restrict__ start_t,
                                                      const float* __restrict__ end_t,
                                                      float* __restrict__ out) {
    __shared__ unsigned char hist[4][Ln * 20];
    int w = threadIdx.x >> 5, lane = threadIdx.x & 31;
    int b = blockIdx.x * 4 + w;
    const float NEG = -3e38f;

    float tcol[TAGS];
#pragma unroll
    for (int i = 0; i < TAGS; i++)
        tcol[i] = (lane < TAGS) ? trans[i * TAGS + lane] : 0.f;

    const float* emrow = g_em + b * Ln * TAGS;
    const int*   idrow = ids + b * Ln;

    float score = (lane < TAGS) ? start_t[lane] + emrow[lane] : NEG;

    for (int t = 1; t < Ln; t++) {
        float em = (lane < TAGS) ? emrow[t * TAGS + lane] : 0.f;
        int mask = (idrow[t] != 0);
        float best = NEG; int bi = 0;
#pragma unroll
        for (int i = 0; i < TAGS; i++) {
            float si = __shfl_sync(0xffffffffu, score, i);
            float v = si + tcol[i];
            if (v > best) { best = v; bi = i; }
        }
        int idx;
        if (mask) { if (lane < TAGS) score = best + em; idx = bi; }
        else      { idx = lane; }
        if (lane < TAGS) hist[w][t * 20 + lane] = (unsigned char)idx;
    }

    float fin = (lane < TAGS) ? score + end_t[lane] : NEG;
    int fid = lane;
#pragma unroll
    for (int off = 16; off; off >>= 1) {
        float ov = __shfl_xor_sync(0xffffffffu, fin, off);
        int   oi = __shfl_xor_sync(0xffffffffu, fid, off);
        if (ov > fin || (ov == fin && oi < fid)) { fin = ov; fid = oi; }
    }
    __syncwarp();

    if (lane == 0) {
        int tag = fid;
        float* orow = out + b * Ln;
        orow[Ln - 1] = (idrow[Ln - 1] != 0) ? (float)tag : 0.f;
        for (int t = Ln - 2; t >= 0; t--) {
            tag = hist[w][(t + 1) * 20 + tag];
            orow[t] = (idrow[t] != 0) ? (float)tag : 0.f;
        }
    }
}

// ---------------- launch ----------------
extern "C" void kernel_launch(void* const* d_in, const int* in_sizes, int n_in,
                              void* d_out, int out_size) {
    const void* p[13];
    for (int i = 0; i < 13; i++) p[i] = 0;
    int c51200 = 0, c65536 = 0, c512 = 0, c17 = 0;
    for (int i = 0; i < n_in; i++) {
        switch (in_sizes[i]) {
            case 131072:  p[0] = d_in[i]; break;
            case 3000000: p[1] = d_in[i]; break;
            case 51200:   p[(c51200++ == 0) ? 2 : 5] = d_in[i]; break;
            case 65536:   p[(c65536++ == 0) ? 3 : 6] = d_in[i]; break;
            case 512:     p[(c512++   == 0) ? 4 : 7] = d_in[i]; break;
            case 4352:    p[8]  = d_in[i]; break;
            case 289:     p[10] = d_in[i]; break;
            case 17: {
                int k = c17++;
                p[(k == 0) ? 9 : ((k == 1) ? 11 : 12)] = d_in[i];
                break;
            }
            default: break;
        }
    }
    const int*   input_ids = (const int*)  p[0];
    const float* emb       = (const float*)p[1];
    const float* Wihf      = (const float*)p[2];
    const float* Whhf      = (const float*)p[3];
    const float* bf        = (const float*)p[4];
    const float* Wihb      = (const float*)p[5];
    const float* Whhb      = (const float*)p[6];
    const float* bb        = (const float*)p[7];
    const float* fcW       = (const float*)p[8];
    const float* fcb       = (const float*)p[9];
    const float* trans     = (const float*)p[10];
    const float* startt    = (const float*)p[11];
    const float* endt      = (const float*)p[12];
    float* out = (float*)d_out;

    prep_kernel<<<64, 256>>>(Wihf, Whhf, bf, Wihb, Whhb, bb);          // launch 1
    proj_kernel<<<dim3(8, (VOCAB + 63) / 64), 256>>>(emb);             // launch 2
    filler_kernel<<<1, 32>>>();                                        // launch 3

    const int lsmem_bytes = (2 * KSM * 512 + 4096 + 512) * (int)sizeof(float)
                          + 4 * Ln * (int)sizeof(int);                 // 190464
    cudaFuncSetAttribute(lstm_kernel, cudaFuncAttributeMaxDynamicSharedMemorySize,
                         lsmem_bytes);
    lstm_kernel<<<128, 512, lsmem_bytes>>>(input_ids);                 // launch 4 (ncu)

    fc_kernel<<<4096, 256>>>(fcW, fcb);                                // launch 5
    viterbi_kernel<<<64, 128>>>(input_ids, trans, startt, endt, out);  // launch 6
}

// round 12
// speedup vs baseline: 1.9358x; 1.0193x over previous
#include <cuda_runtime.h>
#include <math.h>
#include <stdint.h>

#define Bn   256
#define Ln   512
#define VOCAB 30000
#define EMB  100
#define HID  128
#define G4   512          // 4*HID
#define TAGS 17
#define BL   (Bn*Ln)      // 131072
#define KSM  40           // smem W rows per k-half
#define KRG  24           // register W rows per k-half (x2 gate-cols = 48 regs)

// ---------------- scratch (device globals: allocation-free, per rules) ----------------
__device__ float g_proj[VOCAB * 1024];  // per-vocab gate preactivations, both dirs
__device__ float g_hf[BL * HID];        // forward hidden states
__device__ float g_hb[BL * HID];        // backward hidden states
__device__ float g_em[BL * TAGS];       // emissions
__device__ float g_WihT[EMB * 1024];    // W_ih transposed, dirs concatenated on cols
__device__ float g_WhhT[2 * HID * G4];  // W_hh transposed (k-major), per dir
__device__ float g_bias[1024];          // b_f ++ b_b
__device__ int   g_dummy;

// ---------------- packed f32x2 helpers ----------------
__device__ __forceinline__ uint64_t pack2(float lo, float hi) {
    uint64_t r;
    asm("mov.b64 %0, {%1, %2};" : "=l"(r) : "f"(lo), "f"(hi));
    return r;
}
__device__ __forceinline__ float2 unpack2(uint64_t v) {
    float lo, hi;
    asm("mov.b64 {%0, %1}, %2;" : "=f"(lo), "=f"(hi) : "l"(v));
    return make_float2(lo, hi);
}
__device__ __forceinline__ void ffma2(uint64_t& acc, uint64_t a, uint64_t b) {
    asm("fma.rn.f32x2 %0, %1, %2, %0;" : "+l"(acc) : "l"(a), "l"(b));
}

// ---------------- filler (keeps lstm_kernel as the 4th launch for ncu capture) -------
__global__ void filler_kernel() { if (threadIdx.x == 1024) g_dummy = 1; }

// ---------------- prep: transpose weights ----------------
__global__ void prep_kernel(const float* __restrict__ Wihf, const float* __restrict__ Whhf,
                            const float* __restrict__ bf,   const float* __restrict__ Wihb,
                            const float* __restrict__ Whhb, const float* __restrict__ bb) {
    int i = blockIdx.x * blockDim.x + threadIdx.x;
    int stride = gridDim.x * blockDim.x;
    for (int idx = i; idx < EMB * 1024; idx += stride) {
        int e = idx >> 10, c = idx & 1023, d = c >> 9, j = c & 511;
        g_WihT[idx] = (d ? Wihb : Wihf)[j * EMB + e];
    }
    for (int idx = i; idx < 2 * HID * G4; idx += stride) {
        int d = idx >> 16, r = idx & 65535, k = r >> 9, j = r & 511;
        g_WhhT[idx] = (d ? Whhb : Whhf)[j * HID + k];
    }
    for (int idx = i; idx < 1024; idx += stride) {
        int d = idx >> 9, j = idx & 511;
        g_bias[idx] = (d ? bb : bf)[j];
    }
}

// ---------------- vocab projection: proj[v] = emb[v] @ W_ih^T + b (both dirs) ---------
__global__ void __launch_bounds__(256) proj_kernel(const float* __restrict__ emb) {
    __shared__ float xs[64 * EMB];
    int tid = threadIdx.x;
    int rbase = blockIdx.y * 64;
    int cbase = blockIdx.x * 128;

    for (int i = tid; i < 64 * EMB; i += 256) {
        int r = i / EMB, e = i - r * EMB;
        int row = rbase + r;
        xs[i] = (row < VOCAB) ? emb[row * EMB + e] : 0.f;
    }
    __syncthreads();

    int tx = tid & 31, ty = tid >> 5;
    int c0 = cbase + tx * 4;

    uint64_t accA[8], accB[8];
    uint64_t z = pack2(0.f, 0.f);
#pragma unroll
    for (int i = 0; i < 8; i++) { accA[i] = z; accB[i] = z; }

    const float* xrow = xs + (ty * 8) * EMB;
    for (int e = 0; e < EMB; e++) {
        ulonglong2 w2 = *(const ulonglong2*)&g_WihT[e * 1024 + c0];
#pragma unroll
        for (int i = 0; i < 8; i++) {
            float xv = xrow[i * EMB + e];
            uint64_t xx = pack2(xv, xv);
            ffma2(accA[i], xx, w2.x);
            ffma2(accB[i], xx, w2.y);
        }
    }

    float4 bias = *(const float4*)&g_bias[c0];
#pragma unroll
    for (int i = 0; i < 8; i++) {
        int row = rbase + ty * 8 + i;
        if (row < VOCAB) {
            float2 vA = unpack2(accA[i]);
            float2 vB = unpack2(accB[i]);
            float4 o;
            o.x = vA.x + bias.x; o.y = vA.y + bias.y;
            o.z = vB.x + bias.z; o.w = vB.y + bias.w;
            *(float4*)&g_proj[(size_t)row * 1024 + c0] = o;
        }
    }
}

// ---------------- persistent bidirectional LSTM: 512 threads, 4 x f32x2 acc ----------
// Grid 128: dir = bid&1, 4 batch elements per CTA.
// Thread t: half = t>>8 (k-range [half*64, half*64+64)), gate-col pair g0 = 2*(t&255).
// Accumulators packed as f32x2 over batch pairs (b0,b1) and (b2,b3) per gate column:
// the float4 h load provides both f32x2 operands directly. Each packed lane is an
// independent IEEE fp32 FMA chain identical to the unpacked version -> bit-identical.
extern __shared__ float lsmem[];
__device__ __forceinline__ float sigf(float x) { return 1.f / (1.f + expf(-x)); }

__global__ void __launch_bounds__(512, 1) lstm_kernel(const int* __restrict__ ids) {
    float* Wc   = lsmem;                       // 2*KSM*512 floats
    float* part = lsmem + 2 * KSM * 512;       // 4096 floats: [half][gcol][b]
    float* hbuf = part + 4096;                 // 512 floats  [k][b] (16B aligned)
    int*   sids = (int*)(hbuf + 512);          // 2048 ints (pre-scaled id*1024)

    int tid   = threadIdx.x;
    int half  = tid >> 8;                      // k-half
    int g0    = (tid & 255) * 2;               // first of 2 gate columns
    int dir   = blockIdx.x & 1;
    int bbase = (blockIdx.x >> 1) * 4;

    const float* Wt = g_WhhT + dir * (HID * G4);

    // cooperative smem W load: Wc[h][r][c] <- global row h*64 + r  (r < KSM)
    for (int i = tid; i < 2 * KSM * 512; i += 512) {
        int hh = i / (KSM * 512);
        int rem = i - hh * (KSM * 512);
        int r = rem >> 9, c = rem & 511;
        Wc[i] = Wt[(hh * 64 + r) * 512 + c];
    }
    hbuf[tid] = 0.f;
    for (int i = tid; i < 4 * Ln; i += 512) {
        int b = i >> 9, t = i & 511;
        sids[i] = ids[(bbase + b) * Ln + t] * 1024;   // pre-scaled row offset
    }

    // register W rows: global rows half*64 + KSM + j, both gate columns
    float wregA[KRG], wregB[KRG];
#pragma unroll
    for (int j = 0; j < KRG; j++) {
        wregA[j] = Wt[(half * 64 + KSM + j) * 512 + g0];
        wregB[j] = Wt[(half * 64 + KSM + j) * 512 + g0 + 1];
    }

    float creg = 0.f;
    float* hout = dir ? g_hb : g_hf;
    int dcol = dir * 512 + g0;

    __syncthreads();

    int tt0 = dir ? (Ln - 1) : 0;
    float cxA[4], cxB[4], nxA[4], nxB[4];
#pragma unroll
    for (int b = 0; b < 4; b++) { cxA[b] = 0.f; cxB[b] = 0.f; }
    if (half == 0) {
#pragma unroll
        for (int b = 0; b < 4; b++) {
            float2 v = *(const float2*)&g_proj[sids[b * 512 + tt0] + dcol];
            cxA[b] = v.x; cxB[b] = v.y;
        }
    }

    const float*      wp  = Wc + half * (KSM * 512) + g0;
    const ulonglong2* hbp = (const ulonglong2*)hbuf + half * 64;   // this half's k-range
    int b2 = tid & 3, k2 = tid >> 2;                               // phase-2 mapping
    float* partw = part + half * 2048 + g0 * 4;

    for (int s = 0; s < Ln; s++) {
        int tt = dir ? (Ln - 1 - s) : s;
        // prefetch next step's xg (half 0; hidden under the dot-product loop)
#pragma unroll
        for (int b = 0; b < 4; b++) { nxA[b] = 0.f; nxB[b] = 0.f; }
        if (half == 0 && s + 1 < Ln) {
            int tn = dir ? (tt - 1) : (tt + 1);
#pragma unroll
            for (int b = 0; b < 4; b++) {
                float2 v = *(const float2*)&g_proj[sids[b * 512 + tn] + dcol];
                nxA[b] = v.x; nxB[b] = v.y;
            }
        }

        // ---- phase 1: packed partial gate dot products (2 cols x 2 batch-pairs) ----
        uint64_t aA01 = pack2(cxA[0], cxA[1]);
        uint64_t aA23 = pack2(cxA[2], cxA[3]);
        uint64_t aB01 = pack2(cxB[0], cxB[1]);
        uint64_t aB23 = pack2(cxB[2], cxB[3]);
#pragma unroll 8
        for (int r = 0; r < KSM; r++) {
            ulonglong2 hh = hbp[r];                    // (h0,h1) | (h2,h3), 16B broadcast
            float2 w2 = *(const float2*)(wp + r * 512);
            uint64_t wA = pack2(w2.x, w2.x);
            uint64_t wB = pack2(w2.y, w2.y);
            ffma2(aA01, hh.x, wA); ffma2(aA23, hh.y, wA);
            ffma2(aB01, hh.x, wB); ffma2(aB23, hh.y, wB);
        }
#pragma unroll
        for (int j = 0; j < KRG; j++) {
            ulonglong2 hh = hbp[KSM + j];
            uint64_t wA = pack2(wregA[j], wregA[j]);
            uint64_t wB = pack2(wregB[j], wregB[j]);
            ffma2(aA01, hh.x, wA); ffma2(aA23, hh.y, wA);
            ffma2(aB01, hh.x, wB); ffma2(aB23, hh.y, wB);
        }
        float2 vA01 = unpack2(aA01), vA23 = unpack2(aA23);
        float2 vB01 = unpack2(aB01), vB23 = unpack2(aB23);
        float4 pvA; pvA.x = vA01.x; pvA.y = vA01.y; pvA.z = vA23.x; pvA.w = vA23.y;
        float4 pvB; pvB.x = vB01.x; pvB.y = vB01.y; pvB.z = vB23.x; pvB.w = vB23.y;
        *(float4*)partw       = pvA;               // part[half][g0][0..3]
        *(float4*)(partw + 4) = pvB;               // part[half][g0+1][0..3]
        __syncthreads();

        // ---- phase 2: combine halves + cell update, all 512 threads ----
        {
            float gi = part[k2 * 4 + b2]          + part[2048 + k2 * 4 + b2];
            float gf = part[512  + k2 * 4 + b2]   + part[2560 + k2 * 4 + b2];
            float gg = part[1024 + k2 * 4 + b2]   + part[3072 + k2 * 4 + b2];
            float go = part[1536 + k2 * 4 + b2]   + part[3584 + k2 * 4 + b2];
            creg = sigf(gf) * creg + sigf(gi) * tanhf(gg);
            float h = sigf(go) * tanhf(creg);
            hbuf[tid] = h;                         // hbuf[k2*4 + b2] == hbuf[tid]
            hout[((bbase + b2) * Ln + tt) * HID + k2] = h;
        }
        __syncthreads();

#pragma unroll
        for (int b = 0; b < 4; b++) { cxA[b] = nxA[b]; cxB[b] = nxB[b]; }
    }
}

// ---------------- FC: emissions = [h_f, h_b] @ fc_W^T + fc_b ----------------
__global__ void __launch_bounds__(256) fc_kernel(const float* __restrict__ fcW,
                                                 const float* __restrict__ fcb) {
    __shared__ float wsm[TAGS * 256];
    __shared__ float fcb_s[TAGS];
    int tid = threadIdx.x;
    for (int i = tid; i < TAGS * 256; i += 256) wsm[i] = fcW[i];
    if (tid < TAGS) fcb_s[tid] = fcb[tid];
    __syncthreads();

    int lane = tid & 31, warp = tid >> 5;
    int pw = lane >> 3, sl = lane & 7;
    int pos = blockIdx.x * 32 + warp * 4 + pw;

    float4 h4[8];
    const float4* hfp = (const float4*)(g_hf + (size_t)pos * HID);
    const float4* hbp = (const float4*)(g_hb + (size_t)pos * HID);
#pragma unroll
    for (int i = 0; i < 4; i++) h4[i]     = hfp[i * 8 + sl];
#pragma unroll
    for (int i = 0; i < 4; i++) h4[4 + i] = hbp[i * 8 + sl];

    const float4* w4 = (const float4*)wsm;
    float* emrow = g_em + (size_t)pos * TAGS;
#pragma unroll
    for (int t = 0; t < TAGS; t++) {
        float s = 0.f;
#pragma unroll
        for (int i = 0; i < 8; i++) {
            float4 w = w4[t * 64 + i * 8 + sl];
            s += h4[i].x * w.x + h4[i].y * w.y + h4[i].z * w.z + h4[i].w * w.w;
        }
        s += __shfl_xor_sync(0xffffffffu, s, 1);
        s += __shfl_xor_sync(0xffffffffu, s, 2);
        s += __shfl_xor_sync(0xffffffffu, s, 4);
        if (sl == 0) emrow[t] = s + fcb_s[t];
    }
}

// ---------------- Viterbi: one warp per batch element; float32 output ----------------
__global__ void __launch_bounds__(128) viterbi_kernel(const int* __restrict__ ids,
                                                      const float* __restrict__ trans,
                                                      const float* __restrict__ start_t,
                                                      const float* __restrict__ end_t,
                                                      float* __restrict__ out) {
    __shared__ unsigned char hist[4][Ln * 20];
    int w = threadIdx.x >> 5, lane = threadIdx.x & 31;
    int b = blockIdx.x * 4 + w;
    const float NEG = -3e38f;

    float tcol[TAGS];
#pragma unroll
    for (int i = 0; i < TAGS; i++)
        tcol[i] = (lane < TAGS) ? trans[i * TAGS + lane] : 0.f;

    const float* emrow = g_em + b * Ln * TAGS;
    const int*   idrow = ids + b * Ln;

    float score = (lane < TAGS) ? start_t[lane] + emrow[lane] : NEG;

    for (int t = 1; t < Ln; t++) {
        float em = (lane < TAGS) ? emrow[t * TAGS + lane] : 0.f;
        int mask = (idrow[t] != 0);
        float best = NEG; int bi = 0;
#pragma unroll
        for (int i = 0; i < TAGS; i++) {
            float si = __shfl_sync(0xffffffffu, score, i);
            float v = si + tcol[i];
            if (v > best) { best = v; bi = i; }
        }
        int idx;
        if (mask) { if (lane < TAGS) score = best + em; idx = bi; }
        else      { idx = lane; }
        if (lane < TAGS) hist[w][t * 20 + lane] = (unsigned char)idx;
    }

    float fin = (lane < TAGS) ? score + end_t[lane] : NEG;
    int fid = lane;
#pragma unroll
    for (int off = 16; off; off >>= 1) {
        float ov = __shfl_xor_sync(0xffffffffu, fin, off);
        int   oi = __shfl_xor_sync(0xffffffffu, fid, off);
        if (ov > fin || (ov == fin && oi < fid)) { fin = ov; fid = oi; }
    }
    __syncwarp();

    if (lane == 0) {
        int tag = fid;
        float* orow = out + b * Ln;
        orow[Ln - 1] = (idrow[Ln - 1] != 0) ? (float)tag : 0.f;
        for (int t = Ln - 2; t >= 0; t--) {
            tag = hist[w][(t + 1) * 20 + tag];
            orow[t] = (idrow[t] != 0) ? (float)tag : 0.f;
        }
    }
}

// ---------------- launch ----------------
extern "C" void kernel_launch(void* const* d_in, const int* in_sizes, int n_in,
                              void* d_out, int out_size) {
    const void* p[13];
    for (int i = 0; i < 13; i++) p[i] = 0;
    int c51200 = 0, c65536 = 0, c512 = 0, c17 = 0;
    for (int i = 0; i < n_in; i++) {
        switch (in_sizes[i]) {
            case 131072:  p[0] = d_in[i]; break;
            case 3000000: p[1] = d_in[i]; break;
            case 51200:   p[(c51200++ == 0) ? 2 : 5] = d_in[i]; break;
            case 65536:   p[(c65536++ == 0) ? 3 : 6] = d_in[i]; break;
            case 512:     p[(c512++   == 0) ? 4 : 7] = d_in[i]; break;
            case 4352:    p[8]  = d_in[i]; break;
            case 289:     p[10] = d_in[i]; break;
            case 17: {
                int k = c17++;
                p[(k == 0) ? 9 : ((k == 1) ? 11 : 12)] = d_in[i];
                break;
            }
            default: break;
        }
    }
    const int*   input_ids = (const int*)  p[0];
    const float* emb       = (const float*)p[1];
    const float* Wihf      = (const float*)p[2];
    const float* Whhf      = (const float*)p[3];
    const float* bf        = (const float*)p[4];
    const float* Wihb      = (const float*)p[5];
    const float* Whhb      = (const float*)p[6];
    const float* bb        = (const float*)p[7];
    const float* fcW       = (const float*)p[8];
    const float* fcb       = (const float*)p[9];
    const float* trans     = (const float*)p[10];
    const float* startt    = (const float*)p[11];
    const float* endt      = (const float*)p[12];
    float* out = (float*)d_out;

    prep_kernel<<<64, 256>>>(Wihf, Whhf, bf, Wihb, Whhb, bb);          // launch 1
    proj_kernel<<<dim3(8, (VOCAB + 63) / 64), 256>>>(emb);             // launch 2
    filler_kernel<<<1, 32>>>();                                        // launch 3

    const int lsmem_bytes = (2 * KSM * 512 + 4096 + 512) * (int)sizeof(float)
                          + 4 * Ln * (int)sizeof(int);                 // 190464
    cudaFuncSetAttribute(lstm_kernel, cudaFuncAttributeMaxDynamicSharedMemorySize,
                         lsmem_bytes);
    lstm_kernel<<<128, 512, lsmem_bytes>>>(input_ids);                 // launch 4 (ncu)

    fc_kernel<<<4096, 256>>>(fcW, fcb);                                // launch 5
    viterbi_kernel<<<64, 128>>>(input_ids, trans, startt, endt, out);  // launch 6
}

// round 13
// speedup vs baseline: 2.1666x; 1.1192x over previous
#include <cuda_runtime.h>
#include <math.h>
#include <stdint.h>

#define Bn   256
#define Ln   512
#define VOCAB 30000
#define EMB  100
#define HID  128
#define G4   512          // 4*HID
#define TAGS 17
#define BL   (Bn*Ln)      // 131072
#define KSMQ 20           // smem W rows per k-quarter (of 32)
#define KRGQ 12           // register W rows per k-quarter

// ---------------- scratch (device globals: allocation-free, per rules) ----------------
__device__ float g_proj[VOCAB * 1024];  // per-vocab gate preactivations, both dirs
__device__ float g_hf[BL * HID];        // forward hidden states
__device__ float g_hb[BL * HID];        // backward hidden states
__device__ float g_em[BL * TAGS];       // emissions
__device__ float g_WihT[EMB * 1024];    // W_ih transposed, dirs concatenated on cols
__device__ float g_WhhT[2 * HID * G4];  // W_hh transposed (k-major), per dir
__device__ float g_bias[1024];          // b_f ++ b_b
__device__ int   g_dummy;

// ---------------- packed f32x2 helpers ----------------
__device__ __forceinline__ uint64_t pack2(float lo, float hi) {
    uint64_t r;
    asm("mov.b64 %0, {%1, %2};" : "=l"(r) : "f"(lo), "f"(hi));
    return r;
}
__device__ __forceinline__ float2 unpack2(uint64_t v) {
    float lo, hi;
    asm("mov.b64 {%0, %1}, %2;" : "=f"(lo), "=f"(hi) : "l"(v));
    return make_float2(lo, hi);
}
__device__ __forceinline__ void ffma2(uint64_t& acc, uint64_t a, uint64_t b) {
    asm("fma.rn.f32x2 %0, %1, %2, %0;" : "+l"(acc) : "l"(a), "l"(b));
}

// ---------------- filler (keeps lstm_kernel as the 4th launch for ncu capture) -------
__global__ void filler_kernel() { if (threadIdx.x == 1024) g_dummy = 1; }

// ---------------- prep: transpose weights ----------------
__global__ void prep_kernel(const float* __restrict__ Wihf, const float* __restrict__ Whhf,
                            const float* __restrict__ bf,   const float* __restrict__ Wihb,
                            const float* __restrict__ Whhb, const float* __restrict__ bb) {
    int i = blockIdx.x * blockDim.x + threadIdx.x;
    int stride = gridDim.x * blockDim.x;
    for (int idx = i; idx < EMB * 1024; idx += stride) {
        int e = idx >> 10, c = idx & 1023, d = c >> 9, j = c & 511;
        g_WihT[idx] = (d ? Wihb : Wihf)[j * EMB + e];
    }
    for (int idx = i; idx < 2 * HID * G4; idx += stride) {
        int d = idx >> 16, r = idx & 65535, k = r >> 9, j = r & 511;
        g_WhhT[idx] = (d ? Whhb : Whhf)[j * HID + k];
    }
    for (int idx = i; idx < 1024; idx += stride) {
        int d = idx >> 9, j = idx & 511;
        g_bias[idx] = (d ? bb : bf)[j];
    }
}

// ---------------- vocab projection: proj[v] = emb[v] @ W_ih^T + b (both dirs) ---------
__global__ void __launch_bounds__(256) proj_kernel(const float* __restrict__ emb) {
    __shared__ float xs[64 * EMB];
    int tid = threadIdx.x;
    int rbase = blockIdx.y * 64;
    int cbase = blockIdx.x * 128;

    for (int i = tid; i < 64 * EMB; i += 256) {
        int r = i / EMB, e = i - r * EMB;
        int row = rbase + r;
        xs[i] = (row < VOCAB) ? emb[row * EMB + e] : 0.f;
    }
    __syncthreads();

    int tx = tid & 31, ty = tid >> 5;
    int c0 = cbase + tx * 4;

    uint64_t accA[8], accB[8];
    uint64_t z = pack2(0.f, 0.f);
#pragma unroll
    for (int i = 0; i < 8; i++) { accA[i] = z; accB[i] = z; }

    const float* xrow = xs + (ty * 8) * EMB;
    for (int e = 0; e < EMB; e++) {
        ulonglong2 w2 = *(const ulonglong2*)&g_WihT[e * 1024 + c0];
#pragma unroll
        for (int i = 0; i < 8; i++) {
            float xv = xrow[i * EMB + e];
            uint64_t xx = pack2(xv, xv);
            ffma2(accA[i], xx, w2.x);
            ffma2(accB[i], xx, w2.y);
        }
    }

    float4 bias = *(const float4*)&g_bias[c0];
#pragma unroll
    for (int i = 0; i < 8; i++) {
        int row = rbase + ty * 8 + i;
        if (row < VOCAB) {
            float2 vA = unpack2(accA[i]);
            float2 vB = unpack2(accB[i]);
            float4 o;
            o.x = vA.x + bias.x; o.y = vA.y + bias.y;
            o.z = vB.x + bias.z; o.w = vB.y + bias.w;
            *(float4*)&g_proj[(size_t)row * 1024 + c0] = o;
        }
    }
}

// ---------------- persistent bidirectional LSTM: 512 threads, 4-way split-k ----------
// Grid 128: dir = bid&1, 4 batch elements per CTA.
// Thread t: quarter q = t>>7 (k-range [32q, 32q+32)), col group c = t&127, g0 = 4c.
// 16 accumulators (4 cols x 4 batches) packed as 8 f32x2 over batch pairs.
// Per inner iter: 1 LDS.128 h-broadcast (1 wf) + 1 LDS.128 of 4 W cols (4 wf)
// + 8 FFMA2. 12 of 32 k-rows per quarter live in registers (float4 wreg).
// part layout [q][b][col] keeps phase-1 stores and phase-2 reads conflict-free.
extern __shared__ float lsmem[];
__device__ __forceinline__ float sigf(float x) { return 1.f / (1.f + expf(-x)); }

__global__ void __launch_bounds__(512, 1) lstm_kernel(const int* __restrict__ ids) {
    float* Wc   = lsmem;                       // 4*KSMQ*512 floats (163840B)
    float* part = lsmem + 4 * KSMQ * 512;      // 4*2048 floats: [q][b][col]
    float* hbuf = part + 8192;                 // 512 floats [k][b] (16B aligned)
    int*   sids = (int*)(hbuf + 512);          // 2048 ints (pre-scaled id*1024)

    int tid   = threadIdx.x;
    int q     = tid >> 7;                      // k-quarter
    int g0    = (tid & 127) * 4;               // first of 4 gate columns
    int dir   = blockIdx.x & 1;
    int bbase = (blockIdx.x >> 1) * 4;

    const float* Wt = g_WhhT + dir * (HID * G4);

    // cooperative smem W load: Wc[(qq*KSMQ + r)][c] <- W row qq*32 + r (r < KSMQ)
    for (int i = tid; i < 4 * KSMQ * 512; i += 512) {
        int qq = i / (KSMQ * 512);
        int rem = i - qq * (KSMQ * 512);
        int r = rem >> 9, c = rem & 511;
        Wc[i] = Wt[(qq * 32 + r) * 512 + c];
    }
    hbuf[tid] = 0.f;
    for (int i = tid; i < 4 * Ln; i += 512) {
        int b = i >> 9, t = i & 511;
        sids[i] = ids[(bbase + b) * Ln + t] * 1024;   // pre-scaled row offset
    }

    // register W rows: global rows q*32 + KSMQ + j, 4 gate columns each
    float4 wreg[KRGQ];
#pragma unroll
    for (int j = 0; j < KRGQ; j++)
        wreg[j] = *(const float4*)&Wt[(q * 32 + KSMQ + j) * 512 + g0];

    float creg = 0.f;
    float* hout = dir ? g_hb : g_hf;
    int dcol = dir * 512 + g0;

    __syncthreads();

    int tt0 = dir ? (Ln - 1) : 0;
    float4 cx[4], nx[4];                       // xg for 4 batches x 4 cols
#pragma unroll
    for (int b = 0; b < 4; b++) cx[b] = make_float4(0.f, 0.f, 0.f, 0.f);
    if (q == 0) {
#pragma unroll
        for (int b = 0; b < 4; b++)
            cx[b] = *(const float4*)&g_proj[sids[b * 512 + tt0] + dcol];
    }

    const float*      wp  = Wc + q * (KSMQ * 512) + g0;
    const ulonglong2* hbp = (const ulonglong2*)hbuf;       // hbp[k] = h[k][0..3]
    int b2 = tid >> 7, k2 = tid & 127;                     // phase-2 mapping
    float* pq = part + q * 2048;                           // this quarter's partials

    for (int s = 0; s < Ln; s++) {
        int tt = dir ? (Ln - 1 - s) : s;
        // prefetch next step's xg (quarter 0; hidden under the dot-product loop)
#pragma unroll
        for (int b = 0; b < 4; b++) nx[b] = make_float4(0.f, 0.f, 0.f, 0.f);
        if (q == 0 && s + 1 < Ln) {
            int tn = dir ? (tt - 1) : (tt + 1);
#pragma unroll
            for (int b = 0; b < 4; b++)
                nx[b] = *(const float4*)&g_proj[sids[b * 512 + tn] + dcol];
        }

        // ---- phase 1: packed partial dot products (4 cols x 2 batch-pairs) ----
        uint64_t a01[4], a23[4];
        a01[0] = pack2(cx[0].x, cx[1].x); a23[0] = pack2(cx[2].x, cx[3].x);
        a01[1] = pack2(cx[0].y, cx[1].y); a23[1] = pack2(cx[2].y, cx[3].y);
        a01[2] = pack2(cx[0].z, cx[1].z); a23[2] = pack2(cx[2].z, cx[3].z);
        a01[3] = pack2(cx[0].w, cx[1].w); a23[3] = pack2(cx[2].w, cx[3].w);
#pragma unroll
        for (int r = 0; r < KSMQ; r++) {
            ulonglong2 hh = hbp[q * 32 + r];        // (h0,h1)|(h2,h3), 16B broadcast
            float4 w4 = *(const float4*)(wp + r * 512);
            uint64_t w;
            w = pack2(w4.x, w4.x); ffma2(a01[0], hh.x, w); ffma2(a23[0], hh.y, w);
            w = pack2(w4.y, w4.y); ffma2(a01[1], hh.x, w); ffma2(a23[1], hh.y, w);
            w = pack2(w4.z, w4.z); ffma2(a01[2], hh.x, w); ffma2(a23[2], hh.y, w);
            w = pack2(w4.w, w4.w); ffma2(a01[3], hh.x, w); ffma2(a23[3], hh.y, w);
        }
#pragma unroll
        for (int j = 0; j < KRGQ; j++) {
            ulonglong2 hh = hbp[q * 32 + KSMQ + j];
            float4 w4 = wreg[j];
            uint64_t w;
            w = pack2(w4.x, w4.x); ffma2(a01[0], hh.x, w); ffma2(a23[0], hh.y, w);
            w = pack2(w4.y, w4.y); ffma2(a01[1], hh.x, w); ffma2(a23[1], hh.y, w);
            w = pack2(w4.z, w4.z); ffma2(a01[2], hh.x, w); ffma2(a23[2], hh.y, w);
            w = pack2(w4.w, w4.w); ffma2(a01[3], hh.x, w); ffma2(a23[3], hh.y, w);
        }
        // unpack and store per-batch float4s: part[q][b][g0..g0+3]
        float2 u01[4], u23[4];
#pragma unroll
        for (int g = 0; g < 4; g++) { u01[g] = unpack2(a01[g]); u23[g] = unpack2(a23[g]); }
        float4 pv;
        pv.x = u01[0].x; pv.y = u01[1].x; pv.z = u01[2].x; pv.w = u01[3].x;
        *(float4*)(pq + 0 * 512 + g0) = pv;
        pv.x = u01[0].y; pv.y = u01[1].y; pv.z = u01[2].y; pv.w = u01[3].y;
        *(float4*)(pq + 1 * 512 + g0) = pv;
        pv.x = u23[0].x; pv.y = u23[1].x; pv.z = u23[2].x; pv.w = u23[3].x;
        *(float4*)(pq + 2 * 512 + g0) = pv;
        pv.x = u23[0].y; pv.y = u23[1].y; pv.z = u23[2].y; pv.w = u23[3].y;
        *(float4*)(pq + 3 * 512 + g0) = pv;
        __syncthreads();

        // ---- phase 2: combine 4 quarters + cell update for (b2, k2) ----
        {
            const float* pb = part + b2 * 512;
            float gi = pb[k2]        + pb[2048 + k2]        + pb[4096 + k2]        + pb[6144 + k2];
            float gf = pb[128 + k2]  + pb[2048 + 128 + k2]  + pb[4096 + 128 + k2]  + pb[6144 + 128 + k2];
            float gg = pb[256 + k2]  + pb[2048 + 256 + k2]  + pb[4096 + 256 + k2]  + pb[6144 + 256 + k2];
            float go = pb[384 + k2]  + pb[2048 + 384 + k2]  + pb[4096 + 384 + k2]  + pb[6144 + 384 + k2];
            creg = sigf(gf) * creg + sigf(gi) * tanhf(gg);
            float h = sigf(go) * tanhf(creg);
            hbuf[k2 * 4 + b2] = h;
            hout[((bbase + b2) * Ln + tt) * HID + k2] = h;
        }
        __syncthreads();

#pragma unroll
        for (int b = 0; b < 4; b++) cx[b] = nx[b];
    }
}

// ---------------- FC: emissions = [h_f, h_b] @ fc_W^T + fc_b ----------------
__global__ void __launch_bounds__(256) fc_kernel(const float* __restrict__ fcW,
                                                 const float* __restrict__ fcb) {
    __shared__ float wsm[TAGS * 256];
    __shared__ float fcb_s[TAGS];
    int tid = threadIdx.x;
    for (int i = tid; i < TAGS * 256; i += 256) wsm[i] = fcW[i];
    if (tid < TAGS) fcb_s[tid] = fcb[tid];
    __syncthreads();

    int lane = tid & 31, warp = tid >> 5;
    int pw = lane >> 3, sl = lane & 7;
    int pos = blockIdx.x * 32 + warp * 4 + pw;

    float4 h4[8];
    const float4* hfp = (const float4*)(g_hf + (size_t)pos * HID);
    const float4* hbp = (const float4*)(g_hb + (size_t)pos * HID);
#pragma unroll
    for (int i = 0; i < 4; i++) h4[i]     = hfp[i * 8 + sl];
#pragma unroll
    for (int i = 0; i < 4; i++) h4[4 + i] = hbp[i * 8 + sl];

    const float4* w4 = (const float4*)wsm;
    float* emrow = g_em + (size_t)pos * TAGS;
#pragma unroll
    for (int t = 0; t < TAGS; t++) {
        float s = 0.f;
#pragma unroll
        for (int i = 0; i < 8; i++) {
            float4 w = w4[t * 64 + i * 8 + sl];
            s += h4[i].x * w.x + h4[i].y * w.y + h4[i].z * w.z + h4[i].w * w.w;
        }
        s += __shfl_xor_sync(0xffffffffu, s, 1);
        s += __shfl_xor_sync(0xffffffffu, s, 2);
        s += __shfl_xor_sync(0xffffffffu, s, 4);
        if (sl == 0) emrow[t] = s + fcb_s[t];
    }
}

// ---------------- Viterbi: one warp per batch element; float32 output ----------------
__global__ void __launch_bounds__(128) viterbi_kernel(const int* __restrict__ ids,
                                                      const float* __restrict__ trans,
                                                      const float* __restrict__ start_t,
                                                      const float* __restrict__ end_t,
                                                      float* __restrict__ out) {
    __shared__ unsigned char hist[4][Ln * 20];
    int w = threadIdx.x >> 5, lane = threadIdx.x & 31;
    int b = blockIdx.x * 4 + w;
    const float NEG = -3e38f;

    float tcol[TAGS];
#pragma unroll
    for (int i = 0; i < TAGS; i++)
        tcol[i] = (lane < TAGS) ? trans[i * TAGS + lane] : 0.f;

    const float* emrow = g_em + b * Ln * TAGS;
    const int*   idrow = ids + b * Ln;

    float score = (lane < TAGS) ? start_t[lane] + emrow[lane] : NEG;

    for (int t = 1; t < Ln; t++) {
        float em = (lane < TAGS) ? emrow[t * TAGS + lane] : 0.f;
        int mask = (idrow[t] != 0);
        float best = NEG; int bi = 0;
#pragma unroll
        for (int i = 0; i < TAGS; i++) {
            float si = __shfl_sync(0xffffffffu, score, i);
            float v = si + tcol[i];
            if (v > best) { best = v; bi = i; }
        }
        int idx;
        if (mask) { if (lane < TAGS) score = best + em; idx = bi; }
        else      { idx = lane; }
        if (lane < TAGS) hist[w][t * 20 + lane] = (unsigned char)idx;
    }

    float fin = (lane < TAGS) ? score + end_t[lane] : NEG;
    int fid = lane;
#pragma unroll
    for (int off = 16; off; off >>= 1) {
        float ov = __shfl_xor_sync(0xffffffffu, fin, off);
        int   oi = __shfl_xor_sync(0xffffffffu, fid, off);
        if (ov > fin || (ov == fin && oi < fid)) { fin = ov; fid = oi; }
    }
    __syncwarp();

    if (lane == 0) {
        int tag = fid;
        float* orow = out + b * Ln;
        orow[Ln - 1] = (idrow[Ln - 1] != 0) ? (float)tag : 0.f;
        for (int t = Ln - 2; t >= 0; t--) {
            tag = hist[w][(t + 1) * 20 + tag];
            orow[t] = (idrow[t] != 0) ? (float)tag : 0.f;
        }
    }
}

// ---------------- launch ----------------
extern "C" void kernel_launch(void* const* d_in, const int* in_sizes, int n_in,
                              void* d_out, int out_size) {
    const void* p[13];
    for (int i = 0; i < 13; i++) p[i] = 0;
    int c51200 = 0, c65536 = 0, c512 = 0, c17 = 0;
    for (int i = 0; i < n_in; i++) {
        switch (in_sizes[i]) {
            case 131072:  p[0] = d_in[i]; break;
            case 3000000: p[1] = d_in[i]; break;
            case 51200:   p[(c51200++ == 0) ? 2 : 5] = d_in[i]; break;
            case 65536:   p[(c65536++ == 0) ? 3 : 6] = d_in[i]; break;
            case 512:     p[(c512++   == 0) ? 4 : 7] = d_in[i]; break;
            case 4352:    p[8]  = d_in[i]; break;
            case 289:     p[10] = d_in[i]; break;
            case 17: {
                int k = c17++;
                p[(k == 0) ? 9 : ((k == 1) ? 11 : 12)] = d_in[i];
                break;
            }
            default: break;
        }
    }
    const int*   input_ids = (const int*)  p[0];
    const float* emb       = (const float*)p[1];
    const float* Wihf      = (const float*)p[2];
    const float* Whhf      = (const float*)p[3];
    const float* bf        = (const float*)p[4];
    const float* Wihb      = (const float*)p[5];
    const float* Whhb      = (const float*)p[6];
    const float* bb        = (const float*)p[7];
    const float* fcW       = (const float*)p[8];
    const float* fcb       = (const float*)p[9];
    const float* trans     = (const float*)p[10];
    const float* startt    = (const float*)p[11];
    const float* endt      = (const float*)p[12];
    float* out = (float*)d_out;

    prep_kernel<<<64, 256>>>(Wihf, Whhf, bf, Wihb, Whhb, bb);          // launch 1
    proj_kernel<<<dim3(8, (VOCAB + 63) / 64), 256>>>(emb);             // launch 2
    filler_kernel<<<1, 32>>>();                                        // launch 3

    const int lsmem_bytes = (4 * KSMQ * 512 + 8192 + 512) * (int)sizeof(float)
                          + 4 * Ln * (int)sizeof(int);                 // 206848
    cudaFuncSetAttribute(lstm_kernel, cudaFuncAttributeMaxDynamicSharedMemorySize,
                         lsmem_bytes);
    lstm_kernel<<<128, 512, lsmem_bytes>>>(input_ids);                 // launch 4 (ncu)

    fc_kernel<<<4096, 256>>>(fcW, fcb);                                // launch 5
    viterbi_kernel<<<64, 128>>>(input_ids, trans, startt, endt, out);  // launch 6
}

// round 14
// speedup vs baseline: 2.2472x; 1.0372x over previous
#include <cuda_runtime.h>
#include <math.h>
#include <stdint.h>

#define Bn   256
#define Ln   512
#define VOCAB 30000
#define EMB  100
#define HID  128
#define G4   512          // 4*HID
#define TAGS 17
#define BL   (Bn*Ln)      // 131072
#define KSMQ 16           // smem W rows per k-quarter (of 32)
#define KRGQ 16           // register W rows per k-quarter

// ---------------- scratch (device globals: allocation-free, per rules) ----------------
__device__ float g_proj[VOCAB * 1024];  // per-vocab gate preactivations, both dirs
__device__ float g_hf[BL * HID];        // forward hidden states
__device__ float g_hb[BL * HID];        // backward hidden states
__device__ float g_em[BL * TAGS];       // emissions
__device__ float g_WihT[EMB * 1024];    // W_ih transposed, dirs concatenated on cols
__device__ float g_WhhT[2 * HID * G4];  // W_hh transposed (k-major), per dir
__device__ float g_bias[1024];          // b_f ++ b_b
__device__ int   g_dummy;

// ---------------- packed f32x2 helpers ----------------
__device__ __forceinline__ uint64_t pack2(float lo, float hi) {
    uint64_t r;
    asm("mov.b64 %0, {%1, %2};" : "=l"(r) : "f"(lo), "f"(hi));
    return r;
}
__device__ __forceinline__ float2 unpack2(uint64_t v) {
    float lo, hi;
    asm("mov.b64 {%0, %1}, %2;" : "=f"(lo), "=f"(hi) : "l"(v));
    return make_float2(lo, hi);
}
__device__ __forceinline__ void ffma2(uint64_t& acc, uint64_t a, uint64_t b) {
    asm("fma.rn.f32x2 %0, %1, %2, %0;" : "+l"(acc) : "l"(a), "l"(b));
}

// ---------------- filler (keeps lstm_kernel as the 4th launch for ncu capture) -------
__global__ void filler_kernel() { if (threadIdx.x == 1024) g_dummy = 1; }

// ---------------- prep: transpose weights ----------------
__global__ void prep_kernel(const float* __restrict__ Wihf, const float* __restrict__ Whhf,
                            const float* __restrict__ bf,   const float* __restrict__ Wihb,
                            const float* __restrict__ Whhb, const float* __restrict__ bb) {
    int i = blockIdx.x * blockDim.x + threadIdx.x;
    int stride = gridDim.x * blockDim.x;
    for (int idx = i; idx < EMB * 1024; idx += stride) {
        int e = idx >> 10, c = idx & 1023, d = c >> 9, j = c & 511;
        g_WihT[idx] = (d ? Wihb : Wihf)[j * EMB + e];
    }
    for (int idx = i; idx < 2 * HID * G4; idx += stride) {
        int d = idx >> 16, r = idx & 65535, k = r >> 9, j = r & 511;
        g_WhhT[idx] = (d ? Whhb : Whhf)[j * HID + k];
    }
    for (int idx = i; idx < 1024; idx += stride) {
        int d = idx >> 9, j = idx & 511;
        g_bias[idx] = (d ? bb : bf)[j];
    }
}

// ---------------- vocab projection: proj[v] = emb[v] @ W_ih^T + b (both dirs) ---------
__global__ void __launch_bounds__(256) proj_kernel(const float* __restrict__ emb) {
    __shared__ float xs[64 * EMB];
    int tid = threadIdx.x;
    int rbase = blockIdx.y * 64;
    int cbase = blockIdx.x * 128;

    for (int i = tid; i < 64 * EMB; i += 256) {
        int r = i / EMB, e = i - r * EMB;
        int row = rbase + r;
        xs[i] = (row < VOCAB) ? emb[row * EMB + e] : 0.f;
    }
    __syncthreads();

    int tx = tid & 31, ty = tid >> 5;
    int c0 = cbase + tx * 4;

    uint64_t accA[8], accB[8];
    uint64_t z = pack2(0.f, 0.f);
#pragma unroll
    for (int i = 0; i < 8; i++) { accA[i] = z; accB[i] = z; }

    const float* xrow = xs + (ty * 8) * EMB;
    for (int e = 0; e < EMB; e++) {
        ulonglong2 w2 = *(const ulonglong2*)&g_WihT[e * 1024 + c0];
#pragma unroll
        for (int i = 0; i < 8; i++) {
            float xv = xrow[i * EMB + e];
            uint64_t xx = pack2(xv, xv);
            ffma2(accA[i], xx, w2.x);
            ffma2(accB[i], xx, w2.y);
        }
    }

    float4 bias = *(const float4*)&g_bias[c0];
#pragma unroll
    for (int i = 0; i < 8; i++) {
        int row = rbase + ty * 8 + i;
        if (row < VOCAB) {
            float2 vA = unpack2(accA[i]);
            float2 vB = unpack2(accB[i]);
            float4 o;
            o.x = vA.x + bias.x; o.y = vA.y + bias.y;
            o.z = vB.x + bias.z; o.w = vB.y + bias.w;
            *(float4*)&g_proj[(size_t)row * 1024 + c0] = o;
        }
    }
}

// ---------------- persistent bidirectional LSTM: 512 threads, 4-way split-k ----------
// Grid 128: dir = bid&1, 4 batch elements per CTA.
// Phase 1 (thread = quarter q, 4 gate cols): pure partial dot products, acc init 0.
// Phase 2 (thread = (b2, k2)): xg gathered via 4 coalesced LDG.32 issued at step TOP
// (latency hidden under phase 1), combined with the 4 partials as
// ((p0+p1)+(p2+p3)) + xg, then cell update.
extern __shared__ float lsmem[];
__device__ __forceinline__ float sigf(float x) { return 1.f / (1.f + expf(-x)); }

__global__ void __launch_bounds__(512, 1) lstm_kernel(const int* __restrict__ ids) {
    float* Wc   = lsmem;                       // 4*KSMQ*512 floats (131072B)
    float* part = lsmem + 4 * KSMQ * 512;      // 4*2048 floats: [q][b][col]
    float* hbuf = part + 8192;                 // 512 floats [k][b] (16B aligned)
    int*   sids = (int*)(hbuf + 512);          // 2048 ints (pre-scaled id*1024)

    int tid   = threadIdx.x;
    int q     = tid >> 7;                      // k-quarter
    int g0    = (tid & 127) * 4;               // first of 4 gate columns
    int dir   = blockIdx.x & 1;
    int bbase = (blockIdx.x >> 1) * 4;

    const float* Wt = g_WhhT + dir * (HID * G4);

    // cooperative smem W load: Wc[(qq*KSMQ + r)][c] <- W row qq*32 + r (r < KSMQ)
    for (int i = tid; i < 4 * KSMQ * 512; i += 512) {
        int qq = i / (KSMQ * 512);
        int rem = i - qq * (KSMQ * 512);
        int r = rem >> 9, c = rem & 511;
        Wc[i] = Wt[(qq * 32 + r) * 512 + c];
    }
    hbuf[tid] = 0.f;
    for (int i = tid; i < 4 * Ln; i += 512) {
        int b = i >> 9, t = i & 511;
        sids[i] = ids[(bbase + b) * Ln + t] * 1024;   // pre-scaled row offset
    }

    // register W rows: global rows q*32 + KSMQ + j, 4 gate columns each
    float4 wreg[KRGQ];
#pragma unroll
    for (int j = 0; j < KRGQ; j++)
        wreg[j] = *(const float4*)&Wt[(q * 32 + KSMQ + j) * 512 + g0];

    float creg = 0.f;
    float* hout = dir ? g_hb : g_hf;

    const float*      wp  = Wc + q * (KSMQ * 512) + g0;
    const ulonglong2* hbp = (const ulonglong2*)hbuf;       // hbp[k] = h[k][0..3]
    int b2 = tid >> 7, k2 = tid & 127;                     // phase-2 mapping
    int dcol2 = dir * 512 + k2;                            // phase-2 proj column base
    float* pq = part + q * 2048;                           // this quarter's partials

    __syncthreads();

    for (int s = 0; s < Ln; s++) {
        int tt = dir ? (Ln - 1 - s) : s;

        // ---- issue this step's xg gather NOW; consumed in phase 2 (~3000 cyc later) --
        int rowoff = sids[b2 * 512 + tt];
        float xgi = g_proj[rowoff + dcol2];
        float xgf = g_proj[rowoff + dcol2 + 128];
        float xgg = g_proj[rowoff + dcol2 + 256];
        float xgo = g_proj[rowoff + dcol2 + 384];

        // ---- phase 1: packed partial dot products (4 cols x 2 batch-pairs) ----
        uint64_t z = pack2(0.f, 0.f);
        uint64_t a01[4], a23[4];
#pragma unroll
        for (int g = 0; g < 4; g++) { a01[g] = z; a23[g] = z; }
#pragma unroll
        for (int r = 0; r < KSMQ; r++) {
            ulonglong2 hh = hbp[q * 32 + r];        // (h0,h1)|(h2,h3), 16B broadcast
            float4 w4 = *(const float4*)(wp + r * 512);
            uint64_t w;
            w = pack2(w4.x, w4.x); ffma2(a01[0], hh.x, w); ffma2(a23[0], hh.y, w);
            w = pack2(w4.y, w4.y); ffma2(a01[1], hh.x, w); ffma2(a23[1], hh.y, w);
            w = pack2(w4.z, w4.z); ffma2(a01[2], hh.x, w); ffma2(a23[2], hh.y, w);
            w = pack2(w4.w, w4.w); ffma2(a01[3], hh.x, w); ffma2(a23[3], hh.y, w);
        }
#pragma unroll
        for (int j = 0; j < KRGQ; j++) {
            ulonglong2 hh = hbp[q * 32 + KSMQ + j];
            float4 w4 = wreg[j];
            uint64_t w;
            w = pack2(w4.x, w4.x); ffma2(a01[0], hh.x, w); ffma2(a23[0], hh.y, w);
            w = pack2(w4.y, w4.y); ffma2(a01[1], hh.x, w); ffma2(a23[1], hh.y, w);
            w = pack2(w4.z, w4.z); ffma2(a01[2], hh.x, w); ffma2(a23[2], hh.y, w);
            w = pack2(w4.w, w4.w); ffma2(a01[3], hh.x, w); ffma2(a23[3], hh.y, w);
        }
        // unpack and store per-batch float4s: part[q][b][g0..g0+3]
        float2 u01[4], u23[4];
#pragma unroll
        for (int g = 0; g < 4; g++) { u01[g] = unpack2(a01[g]); u23[g] = unpack2(a23[g]); }
        float4 pv;
        pv.x = u01[0].x; pv.y = u01[1].x; pv.z = u01[2].x; pv.w = u01[3].x;
        *(float4*)(pq + 0 * 512 + g0) = pv;
        pv.x = u01[0].y; pv.y = u01[1].y; pv.z = u01[2].y; pv.w = u01[3].y;
        *(float4*)(pq + 1 * 512 + g0) = pv;
        pv.x = u23[0].x; pv.y = u23[1].x; pv.z = u23[2].x; pv.w = u23[3].x;
        *(float4*)(pq + 2 * 512 + g0) = pv;
        pv.x = u23[0].y; pv.y = u23[1].y; pv.z = u23[2].y; pv.w = u23[3].y;
        *(float4*)(pq + 3 * 512 + g0) = pv;
        __syncthreads();

        // ---- phase 2: tree-combine 4 quarters + xg, cell update for (b2, k2) ----
        {
            const float* pb = part + b2 * 512;
            float gi = ((pb[k2]       + pb[2048 + k2])
                      + (pb[4096 + k2] + pb[6144 + k2])) + xgi;
            float gf = ((pb[128 + k2]  + pb[2048 + 128 + k2])
                      + (pb[4096 + 128 + k2] + pb[6144 + 128 + k2])) + xgf;
            float gg = ((pb[256 + k2]  + pb[2048 + 256 + k2])
                      + (pb[4096 + 256 + k2] + pb[6144 + 256 + k2])) + xgg;
            float go = ((pb[384 + k2]  + pb[2048 + 384 + k2])
                      + (pb[4096 + 384 + k2] + pb[6144 + 384 + k2])) + xgo;
            creg = sigf(gf) * creg + sigf(gi) * tanhf(gg);
            float h = sigf(go) * tanhf(creg);
            hbuf[k2 * 4 + b2] = h;
            hout[((bbase + b2) * Ln + tt) * HID + k2] = h;
        }
        __syncthreads();
    }
}

// ---------------- FC: emissions = [h_f, h_b] @ fc_W^T + fc_b ----------------
__global__ void __launch_bounds__(256) fc_kernel(const float* __restrict__ fcW,
                                                 const float* __restrict__ fcb) {
    __shared__ float wsm[TAGS * 256];
    __shared__ float fcb_s[TAGS];
    int tid = threadIdx.x;
    for (int i = tid; i < TAGS * 256; i += 256) wsm[i] = fcW[i];
    if (tid < TAGS) fcb_s[tid] = fcb[tid];
    __syncthreads();

    int lane = tid & 31, warp = tid >> 5;
    int pw = lane >> 3, sl = lane & 7;
    int pos = blockIdx.x * 32 + warp * 4 + pw;

    float4 h4[8];
    const float4* hfp = (const float4*)(g_hf + (size_t)pos * HID);
    const float4* hbp = (const float4*)(g_hb + (size_t)pos * HID);
#pragma unroll
    for (int i = 0; i < 4; i++) h4[i]     = hfp[i * 8 + sl];
#pragma unroll
    for (int i = 0; i < 4; i++) h4[4 + i] = hbp[i * 8 + sl];

    const float4* w4 = (const float4*)wsm;
    float* emrow = g_em + (size_t)pos * TAGS;
#pragma unroll
    for (int t = 0; t < TAGS; t++) {
        float s = 0.f;
#pragma unroll
        for (int i = 0; i < 8; i++) {
            float4 w = w4[t * 64 + i * 8 + sl];
            s += h4[i].x * w.x + h4[i].y * w.y + h4[i].z * w.z + h4[i].w * w.w;
        }
        s += __shfl_xor_sync(0xffffffffu, s, 1);
        s += __shfl_xor_sync(0xffffffffu, s, 2);
        s += __shfl_xor_sync(0xffffffffu, s, 4);
        if (sl == 0) emrow[t] = s + fcb_s[t];
    }
}

// ---------------- Viterbi: one warp per batch element; float32 output ----------------
__global__ void __launch_bounds__(128) viterbi_kernel(const int* __restrict__ ids,
                                                      const float* __restrict__ trans,
                                                      const float* __restrict__ start_t,
                                                      const float* __restrict__ end_t,
                                                      float* __restrict__ out) {
    __shared__ unsigned char hist[4][Ln * 20];
    int w = threadIdx.x >> 5, lane = threadIdx.x & 31;
    int b = blockIdx.x * 4 + w;
    const float NEG = -3e38f;

    float tcol[TAGS];
#pragma unroll
    for (int i = 0; i < TAGS; i++)
        tcol[i] = (lane < TAGS) ? trans[i * TAGS + lane] : 0.f;

    const float* emrow = g_em + b * Ln * TAGS;
    const int*   idrow = ids + b * Ln;

    float score = (lane < TAGS) ? start_t[lane] + emrow[lane] : NEG;

    for (int t = 1; t < Ln; t++) {
        float em = (lane < TAGS) ? emrow[t * TAGS + lane] : 0.f;
        int mask = (idrow[t] != 0);
        float best = NEG; int bi = 0;
#pragma unroll
        for (int i = 0; i < TAGS; i++) {
            float si = __shfl_sync(0xffffffffu, score, i);
            float v = si + tcol[i];
            if (v > best) { best = v; bi = i; }
        }
        int idx;
        if (mask) { if (lane < TAGS) score = best + em; idx = bi; }
        else      { idx = lane; }
        if (lane < TAGS) hist[w][t * 20 + lane] = (unsigned char)idx;
    }

    float fin = (lane < TAGS) ? score + end_t[lane] : NEG;
    int fid = lane;
#pragma unroll
    for (int off = 16; off; off >>= 1) {
        float ov = __shfl_xor_sync(0xffffffffu, fin, off);
        int   oi = __shfl_xor_sync(0xffffffffu, fid, off);
        if (ov > fin || (ov == fin && oi < fid)) { fin = ov; fid = oi; }
    }
    __syncwarp();

    if (lane == 0) {
        int tag = fid;
        float* orow = out + b * Ln;
        orow[Ln - 1] = (idrow[Ln - 1] != 0) ? (float)tag : 0.f;
        for (int t = Ln - 2; t >= 0; t--) {
            tag = hist[w][(t + 1) * 20 + tag];
            orow[t] = (idrow[t] != 0) ? (float)tag : 0.f;
        }
    }
}

// ---------------- launch ----------------
extern "C" void kernel_launch(void* const* d_in, const int* in_sizes, int n_in,
                              void* d_out, int out_size) {
    const void* p[13];
    for (int i = 0; i < 13; i++) p[i] = 0;
    int c51200 = 0, c65536 = 0, c512 = 0, c17 = 0;
    for (int i = 0; i < n_in; i++) {
        switch (in_sizes[i]) {
            case 131072:  p[0] = d_in[i]; break;
            case 3000000: p[1] = d_in[i]; break;
            case 51200:   p[(c51200++ == 0) ? 2 : 5] = d_in[i]; break;
            case 65536:   p[(c65536++ == 0) ? 3 : 6] = d_in[i]; break;
            case 512:     p[(c512++   == 0) ? 4 : 7] = d_in[i]; break;
            case 4352:    p[8]  = d_in[i]; break;
            case 289:     p[10] = d_in[i]; break;
            case 17: {
                int k = c17++;
                p[(k == 0) ? 9 : ((k == 1) ? 11 : 12)] = d_in[i];
                break;
            }
            default: break;
        }
    }
    const int*   input_ids = (const int*)  p[0];
    const float* emb       = (const float*)p[1];
    const float* Wihf      = (const float*)p[2];
    const float* Whhf      = (const float*)p[3];
    const float* bf        = (const float*)p[4];
    const float* Wihb      = (const float*)p[5];
    const float* Whhb      = (const float*)p[6];
    const float* bb        = (const float*)p[7];
    const float* fcW       = (const float*)p[8];
    const float* fcb       = (const float*)p[9];
    const float* trans     = (const float*)p[10];
    const float* startt    = (const float*)p[11];
    const float* endt      = (const float*)p[12];
    float* out = (float*)d_out;

    prep_kernel<<<64, 256>>>(Wihf, Whhf, bf, Wihb, Whhb, bb);          // launch 1
    proj_kernel<<<dim3(8, (VOCAB + 63) / 64), 256>>>(emb);             // launch 2
    filler_kernel<<<1, 32>>>();                                        // launch 3

    const int lsmem_bytes = (4 * KSMQ * 512 + 8192 + 512) * (int)sizeof(float)
                          + 4 * Ln * (int)sizeof(int);                 // 174080
    cudaFuncSetAttribute(lstm_kernel, cudaFuncAttributeMaxDynamicSharedMemorySize,
                         lsmem_bytes);
    lstm_kernel<<<128, 512, lsmem_bytes>>>(input_ids);                 // launch 4 (ncu)

    fc_kernel<<<4096, 256>>>(fcW, fcb);                                // launch 5
    viterbi_kernel<<<64, 128>>>(input_ids, trans, startt, endt, out);  // launch 6
}

// round 15
// speedup vs baseline: 2.3891x; 1.0632x over previous
#include <cuda_runtime.h>
#include <math.h>
#include <stdint.h>

#define Bn   256
#define Ln   512
#define VOCAB 30000
#define EMB  100
#define HID  128
#define G4   512          // 4*HID
#define TAGS 17
#define BL   (Bn*Ln)      // 131072
#define KSMQ 16           // smem W rows per k-quarter (of 32)
#define KRGQ 16           // register W rows per k-quarter

// ---------------- scratch (device globals: allocation-free, per rules) ----------------
__device__ float g_proj[VOCAB * 1024];  // per-vocab gate preactivations, both dirs
__device__ float g_hf[BL * HID];        // forward hidden states
__device__ float g_hb[BL * HID];        // backward hidden states
__device__ float g_em[BL * TAGS];       // emissions
__device__ float g_WihT[EMB * 1024];    // W_ih transposed, dirs concatenated on cols
__device__ float g_WhhT[2 * HID * G4];  // W_hh transposed (k-major), per dir
__device__ float g_bias[1024];          // b_f ++ b_b
__device__ int   g_dummy;

// ---------------- packed f32x2 helpers ----------------
__device__ __forceinline__ uint64_t pack2(float lo, float hi) {
    uint64_t r;
    asm("mov.b64 %0, {%1, %2};" : "=l"(r) : "f"(lo), "f"(hi));
    return r;
}
__device__ __forceinline__ float2 unpack2(uint64_t v) {
    float lo, hi;
    asm("mov.b64 {%0, %1}, %2;" : "=f"(lo), "=f"(hi) : "l"(v));
    return make_float2(lo, hi);
}
__device__ __forceinline__ void ffma2(uint64_t& acc, uint64_t a, uint64_t b) {
    asm("fma.rn.f32x2 %0, %1, %2, %0;" : "+l"(acc) : "l"(a), "l"(b));
}

// ---------------- fast activations (ex2/rcp approx; ~3e-7 rel err, exact saturation) --
__device__ __forceinline__ float fsig(float x) {
    float t, r;
    asm("ex2.approx.ftz.f32 %0, %1;" : "=f"(t) : "f"(-1.4426950408889634f * x));
    asm("rcp.approx.ftz.f32 %0, %1;" : "=f"(r) : "f"(1.0f + t));
    return r;
}
__device__ __forceinline__ float ftanh(float x) {
    float t, r;
    asm("ex2.approx.ftz.f32 %0, %1;" : "=f"(t) : "f"(2.8853900817779268f * x));
    asm("rcp.approx.ftz.f32 %0, %1;" : "=f"(r) : "f"(1.0f + t));
    return 1.0f - 2.0f * r;    // (t-1)/(t+1)
}

// ---------------- filler (keeps lstm_kernel as the 4th launch for ncu capture) -------
__global__ void filler_kernel() { if (threadIdx.x == 1024) g_dummy = 1; }

// ---------------- prep: transpose weights ----------------
__global__ void prep_kernel(const float* __restrict__ Wihf, const float* __restrict__ Whhf,
                            const float* __restrict__ bf,   const float* __restrict__ Wihb,
                            const float* __restrict__ Whhb, const float* __restrict__ bb) {
    int i = blockIdx.x * blockDim.x + threadIdx.x;
    int stride = gridDim.x * blockDim.x;
    for (int idx = i; idx < EMB * 1024; idx += stride) {
        int e = idx >> 10, c = idx & 1023, d = c >> 9, j = c & 511;
        g_WihT[idx] = (d ? Wihb : Wihf)[j * EMB + e];
    }
    for (int idx = i; idx < 2 * HID * G4; idx += stride) {
        int d = idx >> 16, r = idx & 65535, k = r >> 9, j = r & 511;
        g_WhhT[idx] = (d ? Whhb : Whhf)[j * HID + k];
    }
    for (int idx = i; idx < 1024; idx += stride) {
        int d = idx >> 9, j = idx & 511;
        g_bias[idx] = (d ? bb : bf)[j];
    }
}

// ---------------- vocab projection: proj[v] = emb[v] @ W_ih^T + b (both dirs) ---------
__global__ void __launch_bounds__(256) proj_kernel(const float* __restrict__ emb) {
    __shared__ float xs[64 * EMB];
    int tid = threadIdx.x;
    int rbase = blockIdx.y * 64;
    int cbase = blockIdx.x * 128;

    for (int i = tid; i < 64 * EMB; i += 256) {
        int r = i / EMB, e = i - r * EMB;
        int row = rbase + r;
        xs[i] = (row < VOCAB) ? emb[row * EMB + e] : 0.f;
    }
    __syncthreads();

    int tx = tid & 31, ty = tid >> 5;
    int c0 = cbase + tx * 4;

    uint64_t accA[8], accB[8];
    uint64_t z = pack2(0.f, 0.f);
#pragma unroll
    for (int i = 0; i < 8; i++) { accA[i] = z; accB[i] = z; }

    const float* xrow = xs + (ty * 8) * EMB;
    for (int e = 0; e < EMB; e++) {
        ulonglong2 w2 = *(const ulonglong2*)&g_WihT[e * 1024 + c0];
#pragma unroll
        for (int i = 0; i < 8; i++) {
            float xv = xrow[i * EMB + e];
            uint64_t xx = pack2(xv, xv);
            ffma2(accA[i], xx, w2.x);
            ffma2(accB[i], xx, w2.y);
        }
    }

    float4 bias = *(const float4*)&g_bias[c0];
#pragma unroll
    for (int i = 0; i < 8; i++) {
        int row = rbase + ty * 8 + i;
        if (row < VOCAB) {
            float2 vA = unpack2(accA[i]);
            float2 vB = unpack2(accB[i]);
            float4 o;
            o.x = vA.x + bias.x; o.y = vA.y + bias.y;
            o.z = vB.x + bias.z; o.w = vB.y + bias.w;
            *(float4*)&g_proj[(size_t)row * 1024 + c0] = o;
        }
    }
}

// ---------------- persistent bidirectional LSTM: 512 threads, 4-way split-k ----------
// Grid 128: dir = bid&1, 4 batch elements per CTA.
// Phase 1 (thread = quarter q, 4 gate cols): pure partial dot products, acc init 0.
// Phase 2 (thread = (b2, k2)): xg gathered via 4 coalesced LDG.32 issued at step TOP
// (latency hidden under phase 1), combined as ((p0+p1)+(p2+p3)) + xg, then the cell
// update with fast ex2/rcp activations.
extern __shared__ float lsmem[];

__global__ void __launch_bounds__(512, 1) lstm_kernel(const int* __restrict__ ids) {
    float* Wc   = lsmem;                       // 4*KSMQ*512 floats (131072B)
    float* part = lsmem + 4 * KSMQ * 512;      // 4*2048 floats: [q][b][col]
    float* hbuf = part + 8192;                 // 512 floats [k][b] (16B aligned)
    int*   sids = (int*)(hbuf + 512);          // 2048 ints (pre-scaled id*1024)

    int tid   = threadIdx.x;
    int q     = tid >> 7;                      // k-quarter
    int g0    = (tid & 127) * 4;               // first of 4 gate columns
    int dir   = blockIdx.x & 1;
    int bbase = (blockIdx.x >> 1) * 4;

    const float* Wt = g_WhhT + dir * (HID * G4);

    // cooperative smem W load: Wc[(qq*KSMQ + r)][c] <- W row qq*32 + r (r < KSMQ)
    for (int i = tid; i < 4 * KSMQ * 512; i += 512) {
        int qq = i / (KSMQ * 512);
        int rem = i - qq * (KSMQ * 512);
        int r = rem >> 9, c = rem & 511;
        Wc[i] = Wt[(qq * 32 + r) * 512 + c];
    }
    hbuf[tid] = 0.f;
    for (int i = tid; i < 4 * Ln; i += 512) {
        int b = i >> 9, t = i & 511;
        sids[i] = ids[(bbase + b) * Ln + t] * 1024;   // pre-scaled row offset
    }

    // register W rows: global rows q*32 + KSMQ + j, 4 gate columns each
    float4 wreg[KRGQ];
#pragma unroll
    for (int j = 0; j < KRGQ; j++)
        wreg[j] = *(const float4*)&Wt[(q * 32 + KSMQ + j) * 512 + g0];

    float creg = 0.f;
    float* hout = dir ? g_hb : g_hf;

    const float*      wp  = Wc + q * (KSMQ * 512) + g0;
    const ulonglong2* hbp = (const ulonglong2*)hbuf;       // hbp[k] = h[k][0..3]
    int b2 = tid >> 7, k2 = tid & 127;                     // phase-2 mapping
    int dcol2 = dir * 512 + k2;                            // phase-2 proj column base
    float* pq = part + q * 2048;                           // this quarter's partials

    __syncthreads();

    for (int s = 0; s < Ln; s++) {
        int tt = dir ? (Ln - 1 - s) : s;

        // ---- issue this step's xg gather NOW; consumed in phase 2 (~3000 cyc later) --
        int rowoff = sids[b2 * 512 + tt];
        float xgi = g_proj[rowoff + dcol2];
        float xgf = g_proj[rowoff + dcol2 + 128];
        float xgg = g_proj[rowoff + dcol2 + 256];
        float xgo = g_proj[rowoff + dcol2 + 384];

        // ---- phase 1: packed partial dot products (4 cols x 2 batch-pairs) ----
        uint64_t z = pack2(0.f, 0.f);
        uint64_t a01[4], a23[4];
#pragma unroll
        for (int g = 0; g < 4; g++) { a01[g] = z; a23[g] = z; }
#pragma unroll
        for (int r = 0; r < KSMQ; r++) {
            ulonglong2 hh = hbp[q * 32 + r];        // (h0,h1)|(h2,h3), 16B broadcast
            float4 w4 = *(const float4*)(wp + r * 512);
            uint64_t w;
            w = pack2(w4.x, w4.x); ffma2(a01[0], hh.x, w); ffma2(a23[0], hh.y, w);
            w = pack2(w4.y, w4.y); ffma2(a01[1], hh.x, w); ffma2(a23[1], hh.y, w);
            w = pack2(w4.z, w4.z); ffma2(a01[2], hh.x, w); ffma2(a23[2], hh.y, w);
            w = pack2(w4.w, w4.w); ffma2(a01[3], hh.x, w); ffma2(a23[3], hh.y, w);
        }
#pragma unroll
        for (int j = 0; j < KRGQ; j++) {
            ulonglong2 hh = hbp[q * 32 + KSMQ + j];
            float4 w4 = wreg[j];
            uint64_t w;
            w = pack2(w4.x, w4.x); ffma2(a01[0], hh.x, w); ffma2(a23[0], hh.y, w);
            w = pack2(w4.y, w4.y); ffma2(a01[1], hh.x, w); ffma2(a23[1], hh.y, w);
            w = pack2(w4.z, w4.z); ffma2(a01[2], hh.x, w); ffma2(a23[2], hh.y, w);
            w = pack2(w4.w, w4.w); ffma2(a01[3], hh.x, w); ffma2(a23[3], hh.y, w);
        }
        // unpack and store per-batch float4s: part[q][b][g0..g0+3]
        float2 u01[4], u23[4];
#pragma unroll
        for (int g = 0; g < 4; g++) { u01[g] = unpack2(a01[g]); u23[g] = unpack2(a23[g]); }
        float4 pv;
        pv.x = u01[0].x; pv.y = u01[1].x; pv.z = u01[2].x; pv.w = u01[3].x;
        *(float4*)(pq + 0 * 512 + g0) = pv;
        pv.x = u01[0].y; pv.y = u01[1].y; pv.z = u01[2].y; pv.w = u01[3].y;
        *(float4*)(pq + 1 * 512 + g0) = pv;
        pv.x = u23[0].x; pv.y = u23[1].x; pv.z = u23[2].x; pv.w = u23[3].x;
        *(float4*)(pq + 2 * 512 + g0) = pv;
        pv.x = u23[0].y; pv.y = u23[1].y; pv.z = u23[2].y; pv.w = u23[3].y;
        *(float4*)(pq + 3 * 512 + g0) = pv;
        __syncthreads();

        // ---- phase 2: tree-combine 4 quarters + xg, cell update for (b2, k2) ----
        {
            const float* pb = part + b2 * 512;
            float gi = ((pb[k2]       + pb[2048 + k2])
                      + (pb[4096 + k2] + pb[6144 + k2])) + xgi;
            float gf = ((pb[128 + k2]  + pb[2048 + 128 + k2])
                      + (pb[4096 + 128 + k2] + pb[6144 + 128 + k2])) + xgf;
            float gg = ((pb[256 + k2]  + pb[2048 + 256 + k2])
                      + (pb[4096 + 256 + k2] + pb[6144 + 256 + k2])) + xgg;
            float go = ((pb[384 + k2]  + pb[2048 + 384 + k2])
                      + (pb[4096 + 384 + k2] + pb[6144 + 384 + k2])) + xgo;
            creg = fsig(gf) * creg + fsig(gi) * ftanh(gg);
            float h = fsig(go) * ftanh(creg);
            hbuf[k2 * 4 + b2] = h;
            hout[((bbase + b2) * Ln + tt) * HID + k2] = h;
        }
        __syncthreads();
    }
}

// ---------------- FC: emissions = [h_f, h_b] @ fc_W^T + fc_b ----------------
__global__ void __launch_bounds__(256) fc_kernel(const float* __restrict__ fcW,
                                                 const float* __restrict__ fcb) {
    __shared__ float wsm[TAGS * 256];
    __shared__ float fcb_s[TAGS];
    int tid = threadIdx.x;
    for (int i = tid; i < TAGS * 256; i += 256) wsm[i] = fcW[i];
    if (tid < TAGS) fcb_s[tid] = fcb[tid];
    __syncthreads();

    int lane = tid & 31, warp = tid >> 5;
    int pw = lane >> 3, sl = lane & 7;
    int pos = blockIdx.x * 32 + warp * 4 + pw;

    float4 h4[8];
    const float4* hfp = (const float4*)(g_hf + (size_t)pos * HID);
    const float4* hbp = (const float4*)(g_hb + (size_t)pos * HID);
#pragma unroll
    for (int i = 0; i < 4; i++) h4[i]     = hfp[i * 8 + sl];
#pragma unroll
    for (int i = 0; i < 4; i++) h4[4 + i] = hbp[i * 8 + sl];

    const float4* w4 = (const float4*)wsm;
    float* emrow = g_em + (size_t)pos * TAGS;
#pragma unroll
    for (int t = 0; t < TAGS; t++) {
        float s = 0.f;
#pragma unroll
        for (int i = 0; i < 8; i++) {
            float4 w = w4[t * 64 + i * 8 + sl];
            s += h4[i].x * w.x + h4[i].y * w.y + h4[i].z * w.z + h4[i].w * w.w;
        }
        s += __shfl_xor_sync(0xffffffffu, s, 1);
        s += __shfl_xor_sync(0xffffffffu, s, 2);
        s += __shfl_xor_sync(0xffffffffu, s, 4);
        if (sl == 0) emrow[t] = s + fcb_s[t];
    }
}

// ---------------- Viterbi: one warp per batch element; float32 output ----------------
__global__ void __launch_bounds__(128) viterbi_kernel(const int* __restrict__ ids,
                                                      const float* __restrict__ trans,
                                                      const float* __restrict__ start_t,
                                                      const float* __restrict__ end_t,
                                                      float* __restrict__ out) {
    __shared__ unsigned char hist[4][Ln * 20];
    int w = threadIdx.x >> 5, lane = threadIdx.x & 31;
    int b = blockIdx.x * 4 + w;
    const float NEG = -3e38f;

    float tcol[TAGS];
#pragma unroll
    for (int i = 0; i < TAGS; i++)
        tcol[i] = (lane < TAGS) ? trans[i * TAGS + lane] : 0.f;

    const float* emrow = g_em + b * Ln * TAGS;
    const int*   idrow = ids + b * Ln;

    float score = (lane < TAGS) ? start_t[lane] + emrow[lane] : NEG;

    for (int t = 1; t < Ln; t++) {
        float em = (lane < TAGS) ? emrow[t * TAGS + lane] : 0.f;
        int mask = (idrow[t] != 0);
        float best = NEG; int bi = 0;
#pragma unroll
        for (int i = 0; i < TAGS; i++) {
            float si = __shfl_sync(0xffffffffu, score, i);
            float v = si + tcol[i];
            if (v > best) { best = v; bi = i; }
        }
        int idx;
        if (mask) { if (lane < TAGS) score = best + em; idx = bi; }
        else      { idx = lane; }
        if (lane < TAGS) hist[w][t * 20 + lane] = (unsigned char)idx;
    }

    float fin = (lane < TAGS) ? score + end_t[lane] : NEG;
    int fid = lane;
#pragma unroll
    for (int off = 16; off; off >>= 1) {
        float ov = __shfl_xor_sync(0xffffffffu, fin, off);
        int   oi = __shfl_xor_sync(0xffffffffu, fid, off);
        if (ov > fin || (ov == fin && oi < fid)) { fin = ov; fid = oi; }
    }
    __syncwarp();

    if (lane == 0) {
        int tag = fid;
        float* orow = out + b * Ln;
        orow[Ln - 1] = (idrow[Ln - 1] != 0) ? (float)tag : 0.f;
        for (int t = Ln - 2; t >= 0; t--) {
            tag = hist[w][(t + 1) * 20 + tag];
            orow[t] = (idrow[t] != 0) ? (float)tag : 0.f;
        }
    }
}

// ---------------- launch ----------------
extern "C" void kernel_launch(void* const* d_in, const int* in_sizes, int n_in,
                              void* d_out, int out_size) {
    const void* p[13];
    for (int i = 0; i < 13; i++) p[i] = 0;
    int c51200 = 0, c65536 = 0, c512 = 0, c17 = 0;
    for (int i = 0; i < n_in; i++) {
        switch (in_sizes[i]) {
            case 131072:  p[0] = d_in[i]; break;
            case 3000000: p[1] = d_in[i]; break;
            case 51200:   p[(c51200++ == 0) ? 2 : 5] = d_in[i]; break;
            case 65536:   p[(c65536++ == 0) ? 3 : 6] = d_in[i]; break;
            case 512:     p[(c512++   == 0) ? 4 : 7] = d_in[i]; break;
            case 4352:    p[8]  = d_in[i]; break;
            case 289:     p[10] = d_in[i]; break;
            case 17: {
                int k = c17++;
                p[(k == 0) ? 9 : ((k == 1) ? 11 : 12)] = d_in[i];
                break;
            }
            default: break;
        }
    }
    const int*   input_ids = (const int*)  p[0];
    const float* emb       = (const float*)p[1];
    const float* Wihf      = (const float*)p[2];
    const float* Whhf      = (const float*)p[3];
    const float* bf        = (const float*)p[4];
    const float* Wihb      = (const float*)p[5];
    const float* Whhb      = (const float*)p[6];
    const float* bb        = (const float*)p[7];
    const float* fcW       = (const float*)p[8];
    const float* fcb       = (const float*)p[9];
    const float* trans     = (const float*)p[10];
    const float* startt    = (const float*)p[11];
    const float* endt      = (const float*)p[12];
    float* out = (float*)d_out;

    prep_kernel<<<64, 256>>>(Wihf, Whhf, bf, Wihb, Whhb, bb);          // launch 1
    proj_kernel<<<dim3(8, (VOCAB + 63) / 64), 256>>>(emb);             // launch 2
    filler_kernel<<<1, 32>>>();                                        // launch 3

    const int lsmem_bytes = (4 * KSMQ * 512 + 8192 + 512) * (int)sizeof(float)
                          + 4 * Ln * (int)sizeof(int);                 // 174080
    cudaFuncSetAttribute(lstm_kernel, cudaFuncAttributeMaxDynamicSharedMemorySize,
                         lsmem_bytes);
    lstm_kernel<<<128, 512, lsmem_bytes>>>(input_ids);                 // launch 4 (ncu)

    fc_kernel<<<4096, 256>>>(fcW, fcb);                                // launch 5
    viterbi_kernel<<<64, 128>>>(input_ids, trans, startt, endt, out);  // launch 6
}